// round 1
// baseline (speedup 1.0000x reference)
#include <cuda_runtime.h>

// Problem constants
#define B_   2
#define S_   2048
#define D_   1024
#define H_   16
#define DK_  64
#define M_   (B_ * S_)   // 4096 rows in all projection GEMMs

// ---------------------------------------------------------------------------
// Scratch (device globals — no allocation allowed in kernel_launch)
// ---------------------------------------------------------------------------
__device__ float g_Q[B_ * H_ * S_ * DK_];   // [B][H][S][DK]
__device__ float g_K[B_ * H_ * S_ * DK_];
__device__ float g_V[B_ * H_ * S_ * DK_];
__device__ float g_ctx[B_ * S_ * D_];       // [B][S][D] (concat of heads)

// ---------------------------------------------------------------------------
// 128x128x8 fp32 GEMM tile body (256 threads, 8x8 per-thread accumulators)
// C = A(4096x1024) @ W(1024x1024) + bias
// headLayout=0 : C row-major [M][N]
// headLayout=1 : C written as [B][H][S][DK] (n -> (h,dk), m -> (b,s))
// ---------------------------------------------------------------------------
__device__ __forceinline__ void sgemm_body(const float* __restrict__ A,
                                           const float* __restrict__ W,
                                           const float* __restrict__ bias,
                                           float* __restrict__ C,
                                           int headLayout)
{
    __shared__ float As[8][128];
    __shared__ float Ws[8][128];

    const int tid = threadIdx.x;
    const int tx  = tid & 15;      // 0..15  -> 8 output cols (split 4+4)
    const int ty  = tid >> 4;      // 0..15  -> 8 output rows (split 4+4)
    const int bm  = blockIdx.y * 128;
    const int bn  = blockIdx.x * 128;

    float acc[8][8];
#pragma unroll
    for (int i = 0; i < 8; i++)
#pragma unroll
        for (int j = 0; j < 8; j++) acc[i][j] = 0.f;

    // global load mapping
    const int ar = tid >> 1;            // 0..127 : A row within tile
    const int ak = (tid & 1) * 4;       // 0 or 4 : k offset
    const int wr = tid >> 5;            // 0..7   : W k-row within tile
    const int wc = (tid & 31) * 4;      // 0..124 : W col offset

    const float* Aptr = A + (bm + ar) * D_ + ak;
    const float* Wptr = W + wr * D_ + bn + wc;

    for (int k0 = 0; k0 < D_; k0 += 8) {
        float4 av = *(const float4*)(Aptr + k0);
        float4 wv = *(const float4*)(Wptr + (size_t)k0 * D_);

        As[ak + 0][ar] = av.x;
        As[ak + 1][ar] = av.y;
        As[ak + 2][ar] = av.z;
        As[ak + 3][ar] = av.w;
        *(float4*)&Ws[wr][wc] = wv;
        __syncthreads();

#pragma unroll
        for (int kk = 0; kk < 8; kk++) {
            float4 a0 = *(const float4*)&As[kk][ty * 4];
            float4 a1 = *(const float4*)&As[kk][64 + ty * 4];
            float4 b0 = *(const float4*)&Ws[kk][tx * 4];
            float4 b1 = *(const float4*)&Ws[kk][64 + tx * 4];
            float a[8] = {a0.x, a0.y, a0.z, a0.w, a1.x, a1.y, a1.z, a1.w};
            float bb[8] = {b0.x, b0.y, b0.z, b0.w, b1.x, b1.y, b1.z, b1.w};
#pragma unroll
            for (int i = 0; i < 8; i++)
#pragma unroll
                for (int j = 0; j < 8; j++) acc[i][j] += a[i] * bb[j];
        }
        __syncthreads();
    }

    // epilogue
#pragma unroll
    for (int i = 0; i < 8; i++) {
        int row = bm + ((i < 4) ? (ty * 4 + i) : (60 + ty * 4 + i));
#pragma unroll
        for (int jg = 0; jg < 2; jg++) {
            int col = bn + jg * 64 + tx * 4;
            float4 v;
            v.x = acc[i][jg * 4 + 0] + bias[col + 0];
            v.y = acc[i][jg * 4 + 1] + bias[col + 1];
            v.z = acc[i][jg * 4 + 2] + bias[col + 2];
            v.w = acc[i][jg * 4 + 3] + bias[col + 3];
            if (!headLayout) {
                *(float4*)&C[row * D_ + col] = v;
            } else {
                int bb = row >> 11;       // / S_
                int s  = row & (S_ - 1);
                int h  = col >> 6;        // / DK_
                int dk = col & (DK_ - 1);
                *(float4*)&C[(((bb << 4) + h) * S_ + s) * DK_ + dk] = v;
            }
        }
    }
}

// Fused QKV: grid (8, 32, 3); z selects projection
__global__ void __launch_bounds__(256)
qkv_kernel(const float* __restrict__ X,
           const float* __restrict__ Wq, const float* __restrict__ bq,
           const float* __restrict__ Wk, const float* __restrict__ bk,
           const float* __restrict__ Wv, const float* __restrict__ bv)
{
    const float* W; const float* bias; float* dst;
    if (blockIdx.z == 0)      { W = Wq; bias = bq; dst = g_Q; }
    else if (blockIdx.z == 1) { W = Wk; bias = bk; dst = g_K; }
    else                      { W = Wv; bias = bv; dst = g_V; }
    sgemm_body(X, W, bias, dst, 1);
}

// Output projection: grid (8, 32)
__global__ void __launch_bounds__(256)
outproj_kernel(const float* __restrict__ Wo, const float* __restrict__ bo,
               float* __restrict__ out)
{
    sgemm_body(g_ctx, Wo, bo, out, 0);
}

// ---------------------------------------------------------------------------
// Flash-style attention. Per block: 128 Q rows, one (b,h).
// Loop over KV in tiles of 64 rows with online softmax.
// Smem layout (floats):
//   Qs [64][132]  (d-major, scaled by 1/sqrt(DK))
//   Ks [64][68]   (d-major)
//   Ps [64][132]  (scores/probs, k-major -> transposed access is conflict-free)
//   Vs [64][64]   (k-major)
//   mrow/lrow/arow [128]
// ---------------------------------------------------------------------------
#define ATTN_SMEM_FLOATS (64*132 + 64*68 + 64*132 + 64*64 + 3*128)
#define ATTN_SMEM_BYTES  (ATTN_SMEM_FLOATS * 4)   // 102912

__global__ void __launch_bounds__(256)
attn_kernel()
{
    extern __shared__ float sm[];
    float* Qs   = sm;                    // 8448
    float* Ks   = Qs + 64 * 132;         // 4352
    float* Ps   = Ks + 64 * 68;          // 8448
    float* Vs   = Ps + 64 * 132;         // 4096
    float* mrow = Vs + 64 * 64;          // 128
    float* lrow = mrow + 128;            // 128
    float* arow = lrow + 128;            // 128

    const int tid = threadIdx.x;
    const int tx  = tid & 15;   // 4 cols
    const int ty  = tid >> 4;   // 8 rows (split 4+4)
    const int q0  = blockIdx.x * 128;
    const int h   = blockIdx.y;
    const int b   = blockIdx.z;
    const int headBase = ((b * H_) + h) * S_ * DK_;

    const float scale = 0.125f;  // 1/sqrt(64)

    // Load Q tile (scaled), store transposed [d][q]
    for (int i = tid; i < 128 * 16; i += 256) {       // 2048 float4
        int q  = i >> 4;
        int d4 = (i & 15) << 2;
        float4 v = *(const float4*)(&g_Q[headBase + (q0 + q) * DK_ + d4]);
        Qs[(d4 + 0) * 132 + q] = v.x * scale;
        Qs[(d4 + 1) * 132 + q] = v.y * scale;
        Qs[(d4 + 2) * 132 + q] = v.z * scale;
        Qs[(d4 + 3) * 132 + q] = v.w * scale;
    }
    if (tid < 128) { mrow[tid] = -1e30f; lrow[tid] = 0.f; }

    float o[8][4];
#pragma unroll
    for (int i = 0; i < 8; i++)
#pragma unroll
        for (int j = 0; j < 4; j++) o[i][j] = 0.f;

    for (int k0 = 0; k0 < S_; k0 += 64) {
        __syncthreads();   // protects Qs on iter 0, Ks/Vs/Ps reuse afterwards

        // Load K (transposed [d][k]) and V ([k][d])
        for (int i = tid; i < 64 * 16; i += 256) {    // 1024 float4
            int k  = i >> 4;
            int d4 = (i & 15) << 2;
            float4 kv = *(const float4*)(&g_K[headBase + (k0 + k) * DK_ + d4]);
            Ks[(d4 + 0) * 68 + k] = kv.x;
            Ks[(d4 + 1) * 68 + k] = kv.y;
            Ks[(d4 + 2) * 68 + k] = kv.z;
            Ks[(d4 + 3) * 68 + k] = kv.w;
            float4 vv = *(const float4*)(&g_V[headBase + (k0 + k) * DK_ + d4]);
            *(float4*)&Vs[k * 64 + d4] = vv;
        }
        __syncthreads();

        // S = (Q*scale) @ K^T : 8 q-rows x 4 k-cols per thread
        float s[8][4];
#pragma unroll
        for (int i = 0; i < 8; i++)
#pragma unroll
            for (int j = 0; j < 4; j++) s[i][j] = 0.f;

#pragma unroll 8
        for (int d = 0; d < 64; d++) {
            float4 a0 = *(const float4*)&Qs[d * 132 + ty * 4];
            float4 a1 = *(const float4*)&Qs[d * 132 + 64 + ty * 4];
            float4 bk = *(const float4*)&Ks[d * 68 + tx * 4];
            float a[8] = {a0.x, a0.y, a0.z, a0.w, a1.x, a1.y, a1.z, a1.w};
            float bb[4] = {bk.x, bk.y, bk.z, bk.w};
#pragma unroll
            for (int i = 0; i < 8; i++)
#pragma unroll
                for (int j = 0; j < 4; j++) s[i][j] += a[i] * bb[j];
        }

        // Store scores transposed: Ps[k][q]
#pragma unroll
        for (int j = 0; j < 4; j++) {
            int k = tx * 4 + j;
            float4 w0 = make_float4(s[0][j], s[1][j], s[2][j], s[3][j]);
            float4 w1 = make_float4(s[4][j], s[5][j], s[6][j], s[7][j]);
            *(float4*)&Ps[k * 132 + ty * 4]      = w0;
            *(float4*)&Ps[k * 132 + 64 + ty * 4] = w1;
        }
        __syncthreads();

        // Online softmax: one thread per q row
        if (tid < 128) {
            int q = tid;
            float mold = mrow[q];
            float mx = mold;
#pragma unroll 8
            for (int k = 0; k < 64; k++) mx = fmaxf(mx, Ps[k * 132 + q]);
            float alpha = __expf(mold - mx);
            float lsum = 0.f;
#pragma unroll 8
            for (int k = 0; k < 64; k++) {
                float p = __expf(Ps[k * 132 + q] - mx);
                Ps[k * 132 + q] = p;
                lsum += p;
            }
            mrow[q] = mx;
            lrow[q] = lrow[q] * alpha + lsum;
            arow[q] = alpha;
        }
        __syncthreads();

        // Rescale O then accumulate P @ V
        float al[8];
#pragma unroll
        for (int i = 0; i < 8; i++) {
            int q = (i < 4) ? (ty * 4 + i) : (60 + ty * 4 + i);
            al[i] = arow[q];
        }
#pragma unroll
        for (int i = 0; i < 8; i++)
#pragma unroll
            for (int j = 0; j < 4; j++) o[i][j] *= al[i];

#pragma unroll 8
        for (int k = 0; k < 64; k++) {
            float4 p0 = *(const float4*)&Ps[k * 132 + ty * 4];
            float4 p1 = *(const float4*)&Ps[k * 132 + 64 + ty * 4];
            float4 vv = *(const float4*)&Vs[k * 64 + tx * 4];
            float p[8] = {p0.x, p0.y, p0.z, p0.w, p1.x, p1.y, p1.z, p1.w};
            float vb[4] = {vv.x, vv.y, vv.z, vv.w};
#pragma unroll
            for (int i = 0; i < 8; i++)
#pragma unroll
                for (int j = 0; j < 4; j++) o[i][j] += p[i] * vb[j];
        }
    }

    // Normalize and write to concat layout [B][S][D]
#pragma unroll
    for (int i = 0; i < 8; i++) {
        int q = (i < 4) ? (ty * 4 + i) : (60 + ty * 4 + i);
        float inv = 1.0f / lrow[q];
        float4 v = make_float4(o[i][0] * inv, o[i][1] * inv,
                               o[i][2] * inv, o[i][3] * inv);
        *(float4*)&g_ctx[(b * S_ + q0 + q) * D_ + h * DK_ + tx * 4] = v;
    }
}

// ---------------------------------------------------------------------------
// Launch
// ---------------------------------------------------------------------------
extern "C" void kernel_launch(void* const* d_in, const int* in_sizes, int n_in,
                              void* d_out, int out_size)
{
    const float* query = (const float*)d_in[0];
    const float* Wq = (const float*)d_in[1];
    const float* bq = (const float*)d_in[2];
    const float* Wk = (const float*)d_in[3];
    const float* bk = (const float*)d_in[4];
    const float* Wv = (const float*)d_in[5];
    const float* bv = (const float*)d_in[6];
    const float* Wo = (const float*)d_in[7];
    const float* bo = (const float*)d_in[8];
    float* out = (float*)d_out;

    cudaFuncSetAttribute(attn_kernel,
                         cudaFuncAttributeMaxDynamicSharedMemorySize,
                         ATTN_SMEM_BYTES);

    dim3 gemmGrid(D_ / 128, M_ / 128);          // (8, 32)
    qkv_kernel<<<dim3(D_ / 128, M_ / 128, 3), 256>>>(query, Wq, bq, Wk, bk, Wv, bv);
    attn_kernel<<<dim3(S_ / 128, H_, B_), 256, ATTN_SMEM_BYTES>>>();
    outproj_kernel<<<gemmGrid, 256>>>(Wo, bo, out);
}

// round 3
// speedup vs baseline: 2.6645x; 2.6645x over previous
#include <cuda_runtime.h>
#include <cstdint>

// Problem constants
#define B_   2
#define S_   2048
#define D_   1024
#define H_   16
#define DK_  64
#define M_   (B_ * S_)   // 4096

// ---------------------------------------------------------------------------
// Scratch (device globals — no allocation allowed)
// ---------------------------------------------------------------------------
__device__ float g_Xr[M_ * D_];           // tf32-rounded input
__device__ float g_Wt[4 * D_ * D_];       // transposed + tf32-rounded weights [N][K]
__device__ float g_Q[B_ * H_ * S_ * DK_]; // [B][H][S][DK]
__device__ float g_Kv[B_ * H_ * S_ * DK_];
__device__ float g_V[B_ * H_ * S_ * DK_];
__device__ float g_ctx[M_ * D_];          // attention output (tf32-rounded)

// ---------------------------------------------------------------------------
// Helpers
// ---------------------------------------------------------------------------
__device__ __forceinline__ float rna_tf32(float x) {
    float r;
    asm("cvt.rna.tf32.f32 %0, %1;" : "=f"(r) : "f"(x));
    return r;
}

__device__ __forceinline__ uint32_t smem_u32(const void* p) {
    uint32_t a;
    asm("{ .reg .u64 t; cvta.to.shared.u64 t, %1; cvt.u32.u64 %0, t; }"
        : "=r"(a) : "l"(p));
    return a;
}

__device__ __forceinline__ void cp_async16(uint32_t dst, const void* src) {
    asm volatile("cp.async.cg.shared.global [%0], [%1], 16;"
                 :: "r"(dst), "l"(src));
}
#define CP_COMMIT() asm volatile("cp.async.commit_group;" ::: "memory")

// D += A(m16k8) * B(k8n8), tf32 inputs, fp32 accum
__device__ __forceinline__ void mma_tf32(float* c,
                                         uint32_t a0, uint32_t a1,
                                         uint32_t a2, uint32_t a3,
                                         uint32_t b0, uint32_t b1) {
    asm volatile(
        "mma.sync.aligned.m16n8k8.row.col.f32.tf32.tf32.f32 "
        "{%0,%1,%2,%3}, {%4,%5,%6,%7}, {%8,%9}, {%0,%1,%2,%3};"
        : "+f"(c[0]), "+f"(c[1]), "+f"(c[2]), "+f"(c[3])
        : "r"(a0), "r"(a1), "r"(a2), "r"(a3), "r"(b0), "r"(b1));
}

// ---------------------------------------------------------------------------
// Prep: tf32-round input; transpose+round weights to [N][K]
// ---------------------------------------------------------------------------
__global__ void __launch_bounds__(256)
prep_x_kernel(const float* __restrict__ X)
{
    int i = blockIdx.x * 256 + threadIdx.x;
    float4 v = ((const float4*)X)[i];
    v.x = rna_tf32(v.x); v.y = rna_tf32(v.y);
    v.z = rna_tf32(v.z); v.w = rna_tf32(v.w);
    ((float4*)g_Xr)[i] = v;
}

__global__ void __launch_bounds__(256)
prep_w_kernel(const float* __restrict__ Wq, const float* __restrict__ Wk,
              const float* __restrict__ Wv, const float* __restrict__ Wo)
{
    __shared__ float t[32][33];
    int z = blockIdx.z;
    const float* W = (z == 0) ? Wq : (z == 1) ? Wk : (z == 2) ? Wv : Wo;
    float* out = g_Wt + (size_t)z * D_ * D_;
    int n0 = blockIdx.x * 32;
    int k0 = blockIdx.y * 32;
    int x = threadIdx.x, y0 = threadIdx.y;
#pragma unroll
    for (int dy = 0; dy < 32; dy += 8)
        t[y0 + dy][x] = W[(size_t)(k0 + y0 + dy) * D_ + n0 + x];
    __syncthreads();
#pragma unroll
    for (int dy = 0; dy < 32; dy += 8)
        out[(size_t)(n0 + y0 + dy) * D_ + k0 + x] = rna_tf32(t[x][y0 + dy]);
}

// ---------------------------------------------------------------------------
// tf32 mma.sync GEMM: C[M x 1024] = A[M x 1024] @ Wt^T + bias
// CTA tile 128x128, 8 warps (4m x 2n -> 32x64 per warp), K chunks of 32,
// cp.async double-buffered. Smem pad 36 floats/row.
// ---------------------------------------------------------------------------
#define GP 36
#define GEMM_SMEM (2 * 2 * 128 * GP * 4)   // 73728 bytes

__device__ __forceinline__ void tf32_gemm_body(const float* __restrict__ A,
                                               const float* __restrict__ Bt,
                                               const float* __restrict__ bias,
                                               float* __restrict__ C,
                                               int headLayout)
{
    extern __shared__ float sm[];
    float* As = sm;                 // [2][128][GP]
    float* Ws = sm + 2 * 128 * GP;  // [2][128][GP]
    const uint32_t as_u = smem_u32(As);
    const uint32_t ws_u = smem_u32(Ws);

    const int tid  = threadIdx.x;
    const int lane = tid & 31;
    const int w    = tid >> 5;
    const int wm   = w >> 1;        // 0..3
    const int wn   = w & 1;         // 0..1
    const int g    = lane >> 2;     // 0..7
    const int t    = lane & 3;      // 0..3
    const int bm   = blockIdx.y * 128;
    const int bn   = blockIdx.x * 128;

    float acc[2][8][4];
#pragma unroll
    for (int mt = 0; mt < 2; mt++)
#pragma unroll
        for (int nt = 0; nt < 8; nt++)
#pragma unroll
            for (int c = 0; c < 4; c++) acc[mt][nt][c] = 0.f;

    // chunk loader: 128 rows x 32 floats for A and W each (1024 x 16B total each)
    auto load_chunk = [&](int i) {
        const int st = i & 1;
        const int k0 = i * 32;
        const uint32_t ad = as_u + st * 128 * GP * 4;
        const uint32_t wd = ws_u + st * 128 * GP * 4;
#pragma unroll
        for (int j = 0; j < 4; j++) {
            int idx = tid + j * 256;
            int row = idx >> 3, c = idx & 7;
            cp_async16(ad + (row * GP + c * 4) * 4,
                       A + (size_t)(bm + row) * D_ + k0 + c * 4);
        }
#pragma unroll
        for (int j = 0; j < 4; j++) {
            int idx = tid + j * 256;
            int row = idx >> 3, c = idx & 7;
            cp_async16(wd + (row * GP + c * 4) * 4,
                       Bt + (size_t)(bn + row) * D_ + k0 + c * 4);
        }
    };

    load_chunk(0);
    CP_COMMIT();

    for (int i = 0; i < 32; i++) {
        if (i < 31) {
            load_chunk(i + 1);
            CP_COMMIT();
            asm volatile("cp.async.wait_group 1;" ::: "memory");
        } else {
            asm volatile("cp.async.wait_group 0;" ::: "memory");
        }
        __syncthreads();

        const float* a  = As + (i & 1) * 128 * GP;
        const float* bs = Ws + (i & 1) * 128 * GP;

#pragma unroll
        for (int kk = 0; kk < 4; kk++) {
            const int kb = kk * 8;
            uint32_t af[2][4];
#pragma unroll
            for (int mt = 0; mt < 2; mt++) {
                int rb = wm * 32 + mt * 16 + g;
                af[mt][0] = __float_as_uint(a[rb * GP + kb + t]);
                af[mt][1] = __float_as_uint(a[(rb + 8) * GP + kb + t]);
                af[mt][2] = __float_as_uint(a[rb * GP + kb + t + 4]);
                af[mt][3] = __float_as_uint(a[(rb + 8) * GP + kb + t + 4]);
            }
#pragma unroll
            for (int nt = 0; nt < 8; nt++) {
                int nr = wn * 64 + nt * 8 + g;
                uint32_t b0 = __float_as_uint(bs[nr * GP + kb + t]);
                uint32_t b1 = __float_as_uint(bs[nr * GP + kb + t + 4]);
                mma_tf32(acc[0][nt], af[0][0], af[0][1], af[0][2], af[0][3], b0, b1);
                mma_tf32(acc[1][nt], af[1][0], af[1][1], af[1][2], af[1][3], b0, b1);
            }
        }
        __syncthreads();
    }

    // Epilogue
#pragma unroll
    for (int mt = 0; mt < 2; mt++) {
#pragma unroll
        for (int half = 0; half < 2; half++) {
            int row = bm + wm * 32 + mt * 16 + g + half * 8;
#pragma unroll
            for (int nt = 0; nt < 8; nt++) {
                int col = bn + wn * 64 + nt * 8 + 2 * t;
                float2 v;
                v.x = acc[mt][nt][half * 2 + 0] + bias[col + 0];
                v.y = acc[mt][nt][half * 2 + 1] + bias[col + 1];
                if (headLayout) {
                    int bb = row >> 11;
                    int ss = row & (S_ - 1);
                    int h  = col >> 6;
                    int dk = col & (DK_ - 1);
                    *(float2*)&C[(size_t)(((bb << 4) + h) * S_ + ss) * DK_ + dk] = v;
                } else {
                    *(float2*)&C[(size_t)row * D_ + col] = v;
                }
            }
        }
    }
}

__global__ void __launch_bounds__(256)
qkv_t_kernel(const float* __restrict__ bq, const float* __restrict__ bk,
             const float* __restrict__ bv)
{
    const float* bias; float* dst; const float* Bt;
    if (blockIdx.z == 0)      { bias = bq; dst = g_Q;  Bt = g_Wt; }
    else if (blockIdx.z == 1) { bias = bk; dst = g_Kv; Bt = g_Wt + (size_t)D_ * D_; }
    else                      { bias = bv; dst = g_V;  Bt = g_Wt + (size_t)2 * D_ * D_; }
    tf32_gemm_body(g_Xr, Bt, bias, dst, 1);
}

__global__ void __launch_bounds__(256)
outproj_t_kernel(const float* __restrict__ bo, float* __restrict__ out)
{
    tf32_gemm_body(g_ctx, g_Wt + (size_t)3 * D_ * D_, bo, out, 0);
}

// ---------------------------------------------------------------------------
// Attention on mma.sync tf32.
// Block: 128 q-rows x one (b,h). 8 warps, warp w owns q rows [w*16, w*16+16).
// KV tiles of 64. Q fragments register-resident. Smem:
//   Qs/Ps : 128 x 72  (Q tile first, then P reuses the same region)
//   Ks    : 64 x 72   ([k][d])
//   Vs    : 64 x 72   ([k][d])
// ---------------------------------------------------------------------------
#define AP 72
#define ATTN_SMEM ((128 * AP + 64 * AP + 64 * AP) * 4)   // 73728 bytes

__global__ void __launch_bounds__(256)
attn_kernel()
{
    extern __shared__ float sm[];
    float* Qs = sm;              // aliased by Ps after frag extraction
    float* Ps = sm;
    float* Ks = sm + 128 * AP;
    float* Vs = Ks + 64 * AP;

    const int tid  = threadIdx.x;
    const int lane = tid & 31;
    const int w    = tid >> 5;
    const int g    = lane >> 2;     // 0..7
    const int t    = lane & 3;      // 0..3
    const int wq   = w * 16;        // warp's q-row base within tile

    const int q0 = blockIdx.x * 128;
    const int h  = blockIdx.y;
    const int b  = blockIdx.z;
    const int headBase = ((b * H_) + h) * S_ * DK_;
    const float scale = 0.125f;     // 1/sqrt(64)

    // ---- Load Q tile (scaled + tf32-rounded) ----
#pragma unroll
    for (int j = 0; j < 8; j++) {
        int idx = tid + j * 256;            // 2048 float4
        int q  = idx >> 4;
        int c4 = (idx & 15) << 2;
        float4 v = *(const float4*)&g_Q[headBase + (size_t)(q0 + q) * DK_ + c4];
        v.x = rna_tf32(v.x * scale); v.y = rna_tf32(v.y * scale);
        v.z = rna_tf32(v.z * scale); v.w = rna_tf32(v.w * scale);
        *(float4*)&Qs[q * AP + c4] = v;
    }
    __syncthreads();

    // ---- Extract Q fragments (kept in registers for all KV iterations) ----
    uint32_t qa[8][4];
#pragma unroll
    for (int ds = 0; ds < 8; ds++) {
        int kb = ds * 8;
        qa[ds][0] = __float_as_uint(Qs[(wq + g) * AP + kb + t]);
        qa[ds][1] = __float_as_uint(Qs[(wq + g + 8) * AP + kb + t]);
        qa[ds][2] = __float_as_uint(Qs[(wq + g) * AP + kb + t + 4]);
        qa[ds][3] = __float_as_uint(Qs[(wq + g + 8) * AP + kb + t + 4]);
    }

    float m0 = -1e30f, m1 = -1e30f, l0 = 0.f, l1 = 0.f;
    float o[8][4];
#pragma unroll
    for (int nt = 0; nt < 8; nt++)
#pragma unroll
        for (int c = 0; c < 4; c++) o[nt][c] = 0.f;

    for (int k0 = 0; k0 < S_; k0 += 64) {
        __syncthreads();   // everyone done with Ks/Vs (and Qs on iter 0)

        // ---- Load K,V tiles (tf32-rounded), natural [k][d] layout ----
#pragma unroll
        for (int j = 0; j < 4; j++) {
            int idx = tid + j * 256;         // 1024 float4
            int k  = idx >> 4;
            int c4 = (idx & 15) << 2;
            float4 kv = *(const float4*)&g_Kv[headBase + (size_t)(k0 + k) * DK_ + c4];
            kv.x = rna_tf32(kv.x); kv.y = rna_tf32(kv.y);
            kv.z = rna_tf32(kv.z); kv.w = rna_tf32(kv.w);
            *(float4*)&Ks[k * AP + c4] = kv;
            float4 vv = *(const float4*)&g_V[headBase + (size_t)(k0 + k) * DK_ + c4];
            vv.x = rna_tf32(vv.x); vv.y = rna_tf32(vv.y);
            vv.z = rna_tf32(vv.z); vv.w = rna_tf32(vv.w);
            *(float4*)&Vs[k * AP + c4] = vv;
        }
        __syncthreads();

        // ---- S = Q @ K^T : warp tile 16 x 64 ----
        float s[8][4];
#pragma unroll
        for (int nt = 0; nt < 8; nt++)
#pragma unroll
            for (int c = 0; c < 4; c++) s[nt][c] = 0.f;

#pragma unroll
        for (int ds = 0; ds < 8; ds++) {
            int kb = ds * 8;
#pragma unroll
            for (int nt = 0; nt < 8; nt++) {
                uint32_t b0 = __float_as_uint(Ks[(nt * 8 + g) * AP + kb + t]);
                uint32_t b1 = __float_as_uint(Ks[(nt * 8 + g) * AP + kb + t + 4]);
                mma_tf32(s[nt], qa[ds][0], qa[ds][1], qa[ds][2], qa[ds][3], b0, b1);
            }
        }

        // ---- Online softmax (rows g and g+8 of warp tile) ----
        float mx0 = -1e30f, mx1 = -1e30f;
#pragma unroll
        for (int nt = 0; nt < 8; nt++) {
            mx0 = fmaxf(mx0, fmaxf(s[nt][0], s[nt][1]));
            mx1 = fmaxf(mx1, fmaxf(s[nt][2], s[nt][3]));
        }
        mx0 = fmaxf(mx0, __shfl_xor_sync(0xffffffffu, mx0, 1));
        mx0 = fmaxf(mx0, __shfl_xor_sync(0xffffffffu, mx0, 2));
        mx1 = fmaxf(mx1, __shfl_xor_sync(0xffffffffu, mx1, 1));
        mx1 = fmaxf(mx1, __shfl_xor_sync(0xffffffffu, mx1, 2));

        float m0n = fmaxf(m0, mx0);
        float m1n = fmaxf(m1, mx1);
        float alpha0 = __expf(m0 - m0n);
        float alpha1 = __expf(m1 - m1n);
        m0 = m0n; m1 = m1n;

        float sum0 = 0.f, sum1 = 0.f;
        float2* Ps2 = (float2*)Ps;
#pragma unroll
        for (int nt = 0; nt < 8; nt++) {
            float p00 = __expf(s[nt][0] - m0);
            float p01 = __expf(s[nt][1] - m0);
            float p10 = __expf(s[nt][2] - m1);
            float p11 = __expf(s[nt][3] - m1);
            sum0 += p00 + p01;
            sum1 += p10 + p11;
            Ps2[(wq + g) * (AP / 2) + nt * 4 + t]     = make_float2(rna_tf32(p00), rna_tf32(p01));
            Ps2[(wq + g + 8) * (AP / 2) + nt * 4 + t] = make_float2(rna_tf32(p10), rna_tf32(p11));
        }
        sum0 += __shfl_xor_sync(0xffffffffu, sum0, 1);
        sum0 += __shfl_xor_sync(0xffffffffu, sum0, 2);
        sum1 += __shfl_xor_sync(0xffffffffu, sum1, 1);
        sum1 += __shfl_xor_sync(0xffffffffu, sum1, 2);
        l0 = l0 * alpha0 + sum0;
        l1 = l1 * alpha1 + sum1;

        __syncwarp();   // warp-local P write -> read

        // ---- Rescale O, then O += P @ V ----
#pragma unroll
        for (int nt = 0; nt < 8; nt++) {
            o[nt][0] *= alpha0; o[nt][1] *= alpha0;
            o[nt][2] *= alpha1; o[nt][3] *= alpha1;
        }

#pragma unroll
        for (int ks = 0; ks < 8; ks++) {
            int kb = ks * 8;
            uint32_t pa0 = __float_as_uint(Ps[(wq + g) * AP + kb + t]);
            uint32_t pa1 = __float_as_uint(Ps[(wq + g + 8) * AP + kb + t]);
            uint32_t pa2 = __float_as_uint(Ps[(wq + g) * AP + kb + t + 4]);
            uint32_t pa3 = __float_as_uint(Ps[(wq + g + 8) * AP + kb + t + 4]);
#pragma unroll
            for (int nt = 0; nt < 8; nt++) {
                uint32_t b0 = __float_as_uint(Vs[(kb + t) * AP + nt * 8 + g]);
                uint32_t b1 = __float_as_uint(Vs[(kb + t + 4) * AP + nt * 8 + g]);
                mma_tf32(o[nt], pa0, pa1, pa2, pa3, b0, b1);
            }
        }
    }

    // ---- Normalize and store (tf32-rounded for the tf32 output projection) ----
    float inv0 = 1.0f / l0;
    float inv1 = 1.0f / l1;
    int row0 = q0 + wq + g;
    int row1 = row0 + 8;
#pragma unroll
    for (int nt = 0; nt < 8; nt++) {
        int col = h * DK_ + nt * 8 + 2 * t;
        float2 v0 = make_float2(rna_tf32(o[nt][0] * inv0), rna_tf32(o[nt][1] * inv0));
        float2 v1 = make_float2(rna_tf32(o[nt][2] * inv1), rna_tf32(o[nt][3] * inv1));
        *(float2*)&g_ctx[(size_t)(b * S_ + row0) * D_ + col] = v0;
        *(float2*)&g_ctx[(size_t)(b * S_ + row1) * D_ + col] = v1;
    }
}

// ---------------------------------------------------------------------------
// Launch
// ---------------------------------------------------------------------------
extern "C" void kernel_launch(void* const* d_in, const int* in_sizes, int n_in,
                              void* d_out, int out_size)
{
    const float* query = (const float*)d_in[0];
    const float* Wq = (const float*)d_in[1];
    const float* bq = (const float*)d_in[2];
    const float* Wk = (const float*)d_in[3];
    const float* bk = (const float*)d_in[4];
    const float* Wv = (const float*)d_in[5];
    const float* bv = (const float*)d_in[6];
    const float* Wo = (const float*)d_in[7];
    const float* bo = (const float*)d_in[8];
    float* out = (float*)d_out;

    cudaFuncSetAttribute(qkv_t_kernel, cudaFuncAttributeMaxDynamicSharedMemorySize, GEMM_SMEM);
    cudaFuncSetAttribute(outproj_t_kernel, cudaFuncAttributeMaxDynamicSharedMemorySize, GEMM_SMEM);
    cudaFuncSetAttribute(attn_kernel, cudaFuncAttributeMaxDynamicSharedMemorySize, ATTN_SMEM);

    prep_x_kernel<<<(M_ * D_ / 4) / 256, 256>>>(query);
    prep_w_kernel<<<dim3(32, 32, 4), dim3(32, 8)>>>(Wq, Wk, Wv, Wo);

    qkv_t_kernel<<<dim3(8, 32, 3), 256, GEMM_SMEM>>>(bq, bk, bv);
    attn_kernel<<<dim3(S_ / 128, H_, B_), 256, ATTN_SMEM>>>();
    outproj_t_kernel<<<dim3(8, 32), 256, GEMM_SMEM>>>(bo, out);
}

// round 4
// speedup vs baseline: 4.4200x; 1.6588x over previous
#include <cuda_runtime.h>
#include <cuda_bf16.h>
#include <cstdint>

// Problem constants
#define B_   2
#define S_   2048
#define D_   1024
#define H_   16
#define DK_  64
#define M_   (B_ * S_)   // 4096

// ---------------------------------------------------------------------------
// Scratch (device globals)
// ---------------------------------------------------------------------------
__device__ float g_Xr[M_ * D_];                           // tf32-rounded input
__device__ float g_Wt[4 * D_ * D_];                       // [N][K] tf32 weights
__device__ __align__(16) __nv_bfloat16 g_Qb[B_ * H_ * S_ * DK_]; // scaled Q, bf16
__device__ __align__(16) __nv_bfloat16 g_Kb[B_ * H_ * S_ * DK_];
__device__ __align__(16) __nv_bfloat16 g_Vb[B_ * H_ * S_ * DK_];
__device__ float g_ctx[M_ * D_];                          // attn out (tf32-rounded)

// ---------------------------------------------------------------------------
// Helpers
// ---------------------------------------------------------------------------
__device__ __forceinline__ float rna_tf32(float x) {
    float r;
    asm("cvt.rna.tf32.f32 %0, %1;" : "=f"(r) : "f"(x));
    return r;
}

__device__ __forceinline__ uint32_t smem_u32(const void* p) {
    uint32_t a;
    asm("{ .reg .u64 t; cvta.to.shared.u64 t, %1; cvt.u32.u64 %0, t; }"
        : "=r"(a) : "l"(p));
    return a;
}

__device__ __forceinline__ void cp_async16(uint32_t dst, const void* src) {
    asm volatile("cp.async.cg.shared.global [%0], [%1], 16;"
                 :: "r"(dst), "l"(src));
}
#define CP_COMMIT() asm volatile("cp.async.commit_group;" ::: "memory")

// tf32 mma (projections)
__device__ __forceinline__ void mma_tf32(float* c,
                                         uint32_t a0, uint32_t a1,
                                         uint32_t a2, uint32_t a3,
                                         uint32_t b0, uint32_t b1) {
    asm volatile(
        "mma.sync.aligned.m16n8k8.row.col.f32.tf32.tf32.f32 "
        "{%0,%1,%2,%3}, {%4,%5,%6,%7}, {%8,%9}, {%0,%1,%2,%3};"
        : "+f"(c[0]), "+f"(c[1]), "+f"(c[2]), "+f"(c[3])
        : "r"(a0), "r"(a1), "r"(a2), "r"(a3), "r"(b0), "r"(b1));
}

// bf16 mma (attention)
__device__ __forceinline__ void mma_bf16(float* c,
                                         uint32_t a0, uint32_t a1,
                                         uint32_t a2, uint32_t a3,
                                         uint32_t b0, uint32_t b1) {
    asm volatile(
        "mma.sync.aligned.m16n8k16.row.col.f32.bf16.bf16.f32 "
        "{%0,%1,%2,%3}, {%4,%5,%6,%7}, {%8,%9}, {%0,%1,%2,%3};"
        : "+f"(c[0]), "+f"(c[1]), "+f"(c[2]), "+f"(c[3])
        : "r"(a0), "r"(a1), "r"(a2), "r"(a3), "r"(b0), "r"(b1));
}

__device__ __forceinline__ void ldsm_x4(uint32_t& r0, uint32_t& r1,
                                        uint32_t& r2, uint32_t& r3, uint32_t a) {
    asm volatile("ldmatrix.sync.aligned.m8n8.x4.shared.b16 {%0,%1,%2,%3}, [%4];"
                 : "=r"(r0), "=r"(r1), "=r"(r2), "=r"(r3) : "r"(a));
}
__device__ __forceinline__ void ldsm_x4_t(uint32_t& r0, uint32_t& r1,
                                          uint32_t& r2, uint32_t& r3, uint32_t a) {
    asm volatile("ldmatrix.sync.aligned.m8n8.x4.trans.shared.b16 {%0,%1,%2,%3}, [%4];"
                 : "=r"(r0), "=r"(r1), "=r"(r2), "=r"(r3) : "r"(a));
}

__device__ __forceinline__ uint32_t pack_bf16x2(float lo, float hi) {
    __nv_bfloat162 h = __floats2bfloat162_rn(lo, hi);
    return *(uint32_t*)&h;
}

// ---------------------------------------------------------------------------
// Prep: tf32-round input; transpose+round weights to [N][K]
// ---------------------------------------------------------------------------
__global__ void __launch_bounds__(256)
prep_x_kernel(const float* __restrict__ X)
{
    int i = blockIdx.x * 256 + threadIdx.x;
    float4 v = ((const float4*)X)[i];
    v.x = rna_tf32(v.x); v.y = rna_tf32(v.y);
    v.z = rna_tf32(v.z); v.w = rna_tf32(v.w);
    ((float4*)g_Xr)[i] = v;
}

__global__ void __launch_bounds__(256)
prep_w_kernel(const float* __restrict__ Wq, const float* __restrict__ Wk,
              const float* __restrict__ Wv, const float* __restrict__ Wo)
{
    __shared__ float t[32][33];
    int z = blockIdx.z;
    const float* W = (z == 0) ? Wq : (z == 1) ? Wk : (z == 2) ? Wv : Wo;
    float* out = g_Wt + (size_t)z * D_ * D_;
    int n0 = blockIdx.x * 32;
    int k0 = blockIdx.y * 32;
    int x = threadIdx.x, y0 = threadIdx.y;
#pragma unroll
    for (int dy = 0; dy < 32; dy += 8)
        t[y0 + dy][x] = W[(size_t)(k0 + y0 + dy) * D_ + n0 + x];
    __syncthreads();
#pragma unroll
    for (int dy = 0; dy < 32; dy += 8)
        out[(size_t)(n0 + y0 + dy) * D_ + k0 + x] = rna_tf32(t[x][y0 + dy]);
}

// ---------------------------------------------------------------------------
// tf32 mma.sync GEMM (projections): CTA 128x128, 8 warps, cp.async 2-stage.
// outMode: 0 = float row-major (outproj), 1 = bf16 [B][H][S][DK] (k/v),
//          2 = bf16 [B][H][S][DK] scaled by 1/8 (q)
// ---------------------------------------------------------------------------
#define GP 36
#define GEMM_SMEM (2 * 2 * 128 * GP * 4)   // 73728 bytes

__device__ __forceinline__ void tf32_gemm_body(const float* __restrict__ A,
                                               const float* __restrict__ Bt,
                                               const float* __restrict__ bias,
                                               float* __restrict__ Cf,
                                               __nv_bfloat16* __restrict__ Cb,
                                               int outMode)
{
    extern __shared__ float sm[];
    float* As = sm;
    float* Ws = sm + 2 * 128 * GP;
    const uint32_t as_u = smem_u32(As);
    const uint32_t ws_u = smem_u32(Ws);

    const int tid  = threadIdx.x;
    const int lane = tid & 31;
    const int w    = tid >> 5;
    const int wm   = w >> 1;
    const int wn   = w & 1;
    const int g    = lane >> 2;
    const int t    = lane & 3;
    const int bm   = blockIdx.y * 128;
    const int bn   = blockIdx.x * 128;

    float acc[2][8][4];
#pragma unroll
    for (int mt = 0; mt < 2; mt++)
#pragma unroll
        for (int nt = 0; nt < 8; nt++)
#pragma unroll
            for (int c = 0; c < 4; c++) acc[mt][nt][c] = 0.f;

    auto load_chunk = [&](int i) {
        const int st = i & 1;
        const int k0 = i * 32;
        const uint32_t ad = as_u + st * 128 * GP * 4;
        const uint32_t wd = ws_u + st * 128 * GP * 4;
#pragma unroll
        for (int j = 0; j < 4; j++) {
            int idx = tid + j * 256;
            int row = idx >> 3, c = idx & 7;
            cp_async16(ad + (row * GP + c * 4) * 4,
                       A + (size_t)(bm + row) * D_ + k0 + c * 4);
        }
#pragma unroll
        for (int j = 0; j < 4; j++) {
            int idx = tid + j * 256;
            int row = idx >> 3, c = idx & 7;
            cp_async16(wd + (row * GP + c * 4) * 4,
                       Bt + (size_t)(bn + row) * D_ + k0 + c * 4);
        }
    };

    load_chunk(0);
    CP_COMMIT();

    for (int i = 0; i < 32; i++) {
        if (i < 31) {
            load_chunk(i + 1);
            CP_COMMIT();
            asm volatile("cp.async.wait_group 1;" ::: "memory");
        } else {
            asm volatile("cp.async.wait_group 0;" ::: "memory");
        }
        __syncthreads();

        const float* a  = As + (i & 1) * 128 * GP;
        const float* bs = Ws + (i & 1) * 128 * GP;

#pragma unroll
        for (int kk = 0; kk < 4; kk++) {
            const int kb = kk * 8;
            uint32_t af[2][4];
#pragma unroll
            for (int mt = 0; mt < 2; mt++) {
                int rb = wm * 32 + mt * 16 + g;
                af[mt][0] = __float_as_uint(a[rb * GP + kb + t]);
                af[mt][1] = __float_as_uint(a[(rb + 8) * GP + kb + t]);
                af[mt][2] = __float_as_uint(a[rb * GP + kb + t + 4]);
                af[mt][3] = __float_as_uint(a[(rb + 8) * GP + kb + t + 4]);
            }
#pragma unroll
            for (int nt = 0; nt < 8; nt++) {
                int nr = wn * 64 + nt * 8 + g;
                uint32_t b0 = __float_as_uint(bs[nr * GP + kb + t]);
                uint32_t b1 = __float_as_uint(bs[nr * GP + kb + t + 4]);
                mma_tf32(acc[0][nt], af[0][0], af[0][1], af[0][2], af[0][3], b0, b1);
                mma_tf32(acc[1][nt], af[1][0], af[1][1], af[1][2], af[1][3], b0, b1);
            }
        }
        __syncthreads();
    }

    const float qscale = (outMode == 2) ? 0.125f : 1.0f;
#pragma unroll
    for (int mt = 0; mt < 2; mt++) {
#pragma unroll
        for (int half = 0; half < 2; half++) {
            int row = bm + wm * 32 + mt * 16 + g + half * 8;
#pragma unroll
            for (int nt = 0; nt < 8; nt++) {
                int col = bn + wn * 64 + nt * 8 + 2 * t;
                float vx = acc[mt][nt][half * 2 + 0] + bias[col + 0];
                float vy = acc[mt][nt][half * 2 + 1] + bias[col + 1];
                if (outMode == 0) {
                    *(float2*)&Cf[(size_t)row * D_ + col] = make_float2(vx, vy);
                } else {
                    int bb = row >> 11;
                    int ss = row & (S_ - 1);
                    int h  = col >> 6;
                    int dk = col & (DK_ - 1);
                    __nv_bfloat162 hv = __floats2bfloat162_rn(vx * qscale, vy * qscale);
                    *(__nv_bfloat162*)&Cb[(size_t)(((bb << 4) + h) * S_ + ss) * DK_ + dk] = hv;
                }
            }
        }
    }
}

__global__ void __launch_bounds__(256)
qkv_t_kernel(const float* __restrict__ bq, const float* __restrict__ bk,
             const float* __restrict__ bv)
{
    const float* bias; __nv_bfloat16* dst; const float* Bt; int mode;
    if (blockIdx.z == 0)      { bias = bq; dst = g_Qb; Bt = g_Wt;                       mode = 2; }
    else if (blockIdx.z == 1) { bias = bk; dst = g_Kb; Bt = g_Wt + (size_t)D_ * D_;     mode = 1; }
    else                      { bias = bv; dst = g_Vb; Bt = g_Wt + (size_t)2 * D_ * D_; mode = 1; }
    tf32_gemm_body(g_Xr, Bt, bias, nullptr, dst, mode);
}

__global__ void __launch_bounds__(256)
outproj_t_kernel(const float* __restrict__ bo, float* __restrict__ out)
{
    tf32_gemm_body(g_ctx, g_Wt + (size_t)3 * D_ * D_, bo, out, nullptr, 0);
}

// ---------------------------------------------------------------------------
// bf16 flash attention. Block: 128 q x one (b,h), 8 warps (16 q-rows each).
// KV tiles of 64, cp.async double-buffered. ldmatrix fragments, P in regs.
// Smem (bf16): Qs[128][72], Ks[2][64][72], Vs[2][64][72]  = 55296 B
// ---------------------------------------------------------------------------
#define ATS 72
#define ATTN_SMEM ((128 * ATS + 2 * 64 * ATS + 2 * 64 * ATS) * 2)

__global__ void __launch_bounds__(256, 2)
attn_kernel()
{
    extern __shared__ __nv_bfloat16 smb[];
    const uint32_t qs_u = smem_u32(smb);
    const uint32_t ks_u = qs_u + 128 * ATS * 2;
    const uint32_t vs_u = ks_u + 2 * 64 * ATS * 2;

    const int tid  = threadIdx.x;
    const int lane = tid & 31;
    const int w    = tid >> 5;
    const int g    = lane >> 2;
    const int t    = lane & 3;
    const int wq   = w * 16;

    const int q0 = blockIdx.x * 128;
    const int h  = blockIdx.y;
    const int b  = blockIdx.z;
    const size_t headBase = (size_t)((b * H_) + h) * S_ * DK_;

    // Q tile -> smem (cp.async), group 0
#pragma unroll
    for (int j = 0; j < 4; j++) {
        int idx = tid + j * 256;            // 1024 chunks of 16B
        int row = idx >> 3, c = idx & 7;
        cp_async16(qs_u + (row * ATS + c * 8) * 2,
                   g_Qb + headBase + (size_t)(q0 + row) * DK_ + c * 8);
    }
    CP_COMMIT();

    auto load_kv = [&](int iter) {
        int st = iter & 1;
        int k0 = iter * 64;
        uint32_t kd = ks_u + st * 64 * ATS * 2;
        uint32_t vd = vs_u + st * 64 * ATS * 2;
#pragma unroll
        for (int j = 0; j < 2; j++) {
            int idx = tid + j * 256;        // 512 chunks
            int row = idx >> 3, c = idx & 7;
            cp_async16(kd + (row * ATS + c * 8) * 2,
                       g_Kb + headBase + (size_t)(k0 + row) * DK_ + c * 8);
        }
#pragma unroll
        for (int j = 0; j < 2; j++) {
            int idx = tid + j * 256;
            int row = idx >> 3, c = idx & 7;
            cp_async16(vd + (row * ATS + c * 8) * 2,
                       g_Vb + headBase + (size_t)(k0 + row) * DK_ + c * 8);
        }
        CP_COMMIT();
    };
    load_kv(0);   // group 1

    // Wait for Q (leave kv0 in flight), extract Q fragments
    asm volatile("cp.async.wait_group 1;" ::: "memory");
    __syncthreads();

    uint32_t qa[4][4];
#pragma unroll
    for (int kt = 0; kt < 4; kt++) {
        uint32_t addr = qs_u + (((wq + (lane & 15)) * ATS) + kt * 16 + (lane >> 4) * 8) * 2;
        ldsm_x4(qa[kt][0], qa[kt][1], qa[kt][2], qa[kt][3], addr);
    }

    float m0 = -1e30f, m1 = -1e30f, l0 = 0.f, l1 = 0.f;
    float o[8][4];
#pragma unroll
    for (int nt = 0; nt < 8; nt++)
#pragma unroll
        for (int c = 0; c < 4; c++) o[nt][c] = 0.f;

    for (int iter = 0; iter < 32; iter++) {
        if (iter + 1 < 32) {
            load_kv(iter + 1);
            asm volatile("cp.async.wait_group 1;" ::: "memory");
        } else {
            asm volatile("cp.async.wait_group 0;" ::: "memory");
        }
        __syncthreads();

        const int st = iter & 1;
        const uint32_t kb_base = ks_u + st * 64 * ATS * 2;
        const uint32_t vb_base = vs_u + st * 64 * ATS * 2;

        // ---- S = Q @ K^T ----
        float s[8][4];
#pragma unroll
        for (int nt = 0; nt < 8; nt++)
#pragma unroll
            for (int c = 0; c < 4; c++) s[nt][c] = 0.f;

#pragma unroll
        for (int kt = 0; kt < 4; kt++) {
#pragma unroll
            for (int ntp = 0; ntp < 4; ntp++) {
                uint32_t r0, r1, r2, r3;
                uint32_t addr = kb_base +
                    ((ntp * 16 + (lane >> 4) * 8 + (lane & 7)) * ATS +
                     kt * 16 + ((lane >> 3) & 1) * 8) * 2;
                ldsm_x4(r0, r1, r2, r3, addr);
                mma_bf16(s[2 * ntp],     qa[kt][0], qa[kt][1], qa[kt][2], qa[kt][3], r0, r1);
                mma_bf16(s[2 * ntp + 1], qa[kt][0], qa[kt][1], qa[kt][2], qa[kt][3], r2, r3);
            }
        }

        // ---- Online softmax (rows g, g+8) ----
        float mx0 = -1e30f, mx1 = -1e30f;
#pragma unroll
        for (int nt = 0; nt < 8; nt++) {
            mx0 = fmaxf(mx0, fmaxf(s[nt][0], s[nt][1]));
            mx1 = fmaxf(mx1, fmaxf(s[nt][2], s[nt][3]));
        }
        mx0 = fmaxf(mx0, __shfl_xor_sync(0xffffffffu, mx0, 1));
        mx0 = fmaxf(mx0, __shfl_xor_sync(0xffffffffu, mx0, 2));
        mx1 = fmaxf(mx1, __shfl_xor_sync(0xffffffffu, mx1, 1));
        mx1 = fmaxf(mx1, __shfl_xor_sync(0xffffffffu, mx1, 2));

        float m0n = fmaxf(m0, mx0);
        float m1n = fmaxf(m1, mx1);
        float alpha0 = __expf(m0 - m0n);
        float alpha1 = __expf(m1 - m1n);
        m0 = m0n; m1 = m1n;

        uint32_t pf[8][2];
        float sum0 = 0.f, sum1 = 0.f;
#pragma unroll
        for (int nt = 0; nt < 8; nt++) {
            float p00 = __expf(s[nt][0] - m0);
            float p01 = __expf(s[nt][1] - m0);
            float p10 = __expf(s[nt][2] - m1);
            float p11 = __expf(s[nt][3] - m1);
            sum0 += p00 + p01;
            sum1 += p10 + p11;
            pf[nt][0] = pack_bf16x2(p00, p01);
            pf[nt][1] = pack_bf16x2(p10, p11);
        }
        sum0 += __shfl_xor_sync(0xffffffffu, sum0, 1);
        sum0 += __shfl_xor_sync(0xffffffffu, sum0, 2);
        sum1 += __shfl_xor_sync(0xffffffffu, sum1, 1);
        sum1 += __shfl_xor_sync(0xffffffffu, sum1, 2);
        l0 = l0 * alpha0 + sum0;
        l1 = l1 * alpha1 + sum1;

        // ---- O = O*alpha + P @ V ----
#pragma unroll
        for (int nt = 0; nt < 8; nt++) {
            o[nt][0] *= alpha0; o[nt][1] *= alpha0;
            o[nt][2] *= alpha1; o[nt][3] *= alpha1;
        }

#pragma unroll
        for (int kt = 0; kt < 4; kt++) {
            uint32_t a0 = pf[2 * kt][0];
            uint32_t a1 = pf[2 * kt][1];
            uint32_t a2 = pf[2 * kt + 1][0];
            uint32_t a3 = pf[2 * kt + 1][1];
#pragma unroll
            for (int ntp = 0; ntp < 4; ntp++) {
                uint32_t r0, r1, r2, r3;
                uint32_t addr = vb_base +
                    ((kt * 16 + ((lane >> 3) & 1) * 8 + (lane & 7)) * ATS +
                     ntp * 16 + (lane >> 4) * 8) * 2;
                ldsm_x4_t(r0, r1, r2, r3, addr);
                mma_bf16(o[2 * ntp],     a0, a1, a2, a3, r0, r1);
                mma_bf16(o[2 * ntp + 1], a0, a1, a2, a3, r2, r3);
            }
        }
        __syncthreads();   // all reads of this stage done before it is refilled
    }

    // ---- Normalize, tf32-round, store to ctx ----
    float inv0 = 1.0f / l0;
    float inv1 = 1.0f / l1;
    int row0 = b * S_ + q0 + wq + g;
    int row1 = row0 + 8;
#pragma unroll
    for (int nt = 0; nt < 8; nt++) {
        int col = h * DK_ + nt * 8 + 2 * t;
        float2 v0 = make_float2(rna_tf32(o[nt][0] * inv0), rna_tf32(o[nt][1] * inv0));
        float2 v1 = make_float2(rna_tf32(o[nt][2] * inv1), rna_tf32(o[nt][3] * inv1));
        *(float2*)&g_ctx[(size_t)row0 * D_ + col] = v0;
        *(float2*)&g_ctx[(size_t)row1 * D_ + col] = v1;
    }
}

// ---------------------------------------------------------------------------
// Launch
// ---------------------------------------------------------------------------
extern "C" void kernel_launch(void* const* d_in, const int* in_sizes, int n_in,
                              void* d_out, int out_size)
{
    const float* query = (const float*)d_in[0];
    const float* Wq = (const float*)d_in[1];
    const float* bq = (const float*)d_in[2];
    const float* Wk = (const float*)d_in[3];
    const float* bk = (const float*)d_in[4];
    const float* Wv = (const float*)d_in[5];
    const float* bv = (const float*)d_in[6];
    const float* Wo = (const float*)d_in[7];
    const float* bo = (const float*)d_in[8];
    float* out = (float*)d_out;

    cudaFuncSetAttribute(qkv_t_kernel, cudaFuncAttributeMaxDynamicSharedMemorySize, GEMM_SMEM);
    cudaFuncSetAttribute(outproj_t_kernel, cudaFuncAttributeMaxDynamicSharedMemorySize, GEMM_SMEM);
    cudaFuncSetAttribute(attn_kernel, cudaFuncAttributeMaxDynamicSharedMemorySize, ATTN_SMEM);

    prep_x_kernel<<<(M_ * D_ / 4) / 256, 256>>>(query);
    prep_w_kernel<<<dim3(32, 32, 4), dim3(32, 8)>>>(Wq, Wk, Wv, Wo);

    qkv_t_kernel<<<dim3(8, 32, 3), 256, GEMM_SMEM>>>(bq, bk, bv);
    attn_kernel<<<dim3(S_ / 128, H_, B_), 256, ATTN_SMEM>>>();
    outproj_t_kernel<<<dim3(8, 32), 256, GEMM_SMEM>>>(bo, out);
}

// round 6
// speedup vs baseline: 6.1574x; 1.3931x over previous
#include <cuda_runtime.h>
#include <cuda_fp16.h>
#include <cstdint>

// Problem constants
#define B_   2
#define S_   2048
#define D_   1024
#define H_   16
#define DK_  64
#define M_   (B_ * S_)   // 4096

#define LOG2E 1.4426950408889634f

// ---------------------------------------------------------------------------
// Scratch (device globals)
// ---------------------------------------------------------------------------
__device__ __align__(16) __half g_Xh[M_ * D_];            // fp16 input
__device__ __align__(16) __half g_Wh[4 * D_ * D_];        // [N][K] fp16 weights (q,k,v,o)
__device__ __align__(16) __half g_Qh[B_ * H_ * S_ * DK_]; // Q * (1/8 * log2e)
__device__ __align__(16) __half g_Kh[B_ * H_ * S_ * DK_];
__device__ __align__(16) __half g_Vh[B_ * H_ * S_ * DK_];
__device__ __align__(16) __half g_ctx[M_ * D_];           // attention out, fp16

// ---------------------------------------------------------------------------
// Helpers
// ---------------------------------------------------------------------------
__device__ __forceinline__ uint32_t smem_u32(const void* p) {
    uint32_t a;
    asm("{ .reg .u64 t; cvta.to.shared.u64 t, %1; cvt.u32.u64 %0, t; }"
        : "=r"(a) : "l"(p));
    return a;
}

__device__ __forceinline__ void cp_async16(uint32_t dst, const void* src) {
    asm volatile("cp.async.cg.shared.global [%0], [%1], 16;"
                 :: "r"(dst), "l"(src));
}
#define CP_COMMIT() asm volatile("cp.async.commit_group;" ::: "memory")

__device__ __forceinline__ float ex2f(float x) {
    float r;
    asm("ex2.approx.f32 %0, %1;" : "=f"(r) : "f"(x));
    return r;
}

// fp16 mma, fp32 accumulate
__device__ __forceinline__ void mma_f16(float* c,
                                        uint32_t a0, uint32_t a1,
                                        uint32_t a2, uint32_t a3,
                                        uint32_t b0, uint32_t b1) {
    asm volatile(
        "mma.sync.aligned.m16n8k16.row.col.f32.f16.f16.f32 "
        "{%0,%1,%2,%3}, {%4,%5,%6,%7}, {%8,%9}, {%0,%1,%2,%3};"
        : "+f"(c[0]), "+f"(c[1]), "+f"(c[2]), "+f"(c[3])
        : "r"(a0), "r"(a1), "r"(a2), "r"(a3), "r"(b0), "r"(b1));
}

__device__ __forceinline__ void ldsm_x4(uint32_t& r0, uint32_t& r1,
                                        uint32_t& r2, uint32_t& r3, uint32_t a) {
    asm volatile("ldmatrix.sync.aligned.m8n8.x4.shared.b16 {%0,%1,%2,%3}, [%4];"
                 : "=r"(r0), "=r"(r1), "=r"(r2), "=r"(r3) : "r"(a));
}
__device__ __forceinline__ void ldsm_x4_t(uint32_t& r0, uint32_t& r1,
                                          uint32_t& r2, uint32_t& r3, uint32_t a) {
    asm volatile("ldmatrix.sync.aligned.m8n8.x4.trans.shared.b16 {%0,%1,%2,%3}, [%4];"
                 : "=r"(r0), "=r"(r1), "=r"(r2), "=r"(r3) : "r"(a));
}

__device__ __forceinline__ uint32_t pack_h2(float lo, float hi) {
    __half2 h = __floats2half2_rn(lo, hi);
    return *(uint32_t*)&h;
}

// ---------------------------------------------------------------------------
// Prep: fp32 -> fp16 input; transpose + fp16 weights to [N][K]
// ---------------------------------------------------------------------------
__global__ void __launch_bounds__(256)
prep_x_kernel(const float* __restrict__ X)
{
    int i = blockIdx.x * 256 + threadIdx.x;   // 8 elems per thread
    float4 v0 = ((const float4*)X)[2 * i];
    float4 v1 = ((const float4*)X)[2 * i + 1];
    uint4 o;
    o.x = pack_h2(v0.x, v0.y);
    o.y = pack_h2(v0.z, v0.w);
    o.z = pack_h2(v1.x, v1.y);
    o.w = pack_h2(v1.z, v1.w);
    ((uint4*)g_Xh)[i] = o;
}

__global__ void __launch_bounds__(256)
prep_w_kernel(const float* __restrict__ Wq, const float* __restrict__ Wk,
              const float* __restrict__ Wv, const float* __restrict__ Wo)
{
    __shared__ float t[32][33];
    int z = blockIdx.z;
    const float* W = (z == 0) ? Wq : (z == 1) ? Wk : (z == 2) ? Wv : Wo;
    __half* out = g_Wh + (size_t)z * D_ * D_;
    int n0 = blockIdx.x * 32;
    int k0 = blockIdx.y * 32;
    int x = threadIdx.x, y0 = threadIdx.y;    // block (32, 8)
#pragma unroll
    for (int dy = 0; dy < 32; dy += 8)
        t[y0 + dy][x] = W[(size_t)(k0 + y0 + dy) * D_ + n0 + x];
    __syncthreads();
#pragma unroll
    for (int dy = 0; dy < 32; dy += 8)
        out[(size_t)(n0 + y0 + dy) * D_ + k0 + x] = __float2half_rn(t[x][y0 + dy]);
}

// ---------------------------------------------------------------------------
// fp16 mma GEMM: C[M x 1024] = A[M x 1024] @ Wt^T + bias
// CTA 128x128, 8 warps (4m x 2n -> 32x64 each), K chunks of 64, 2-stage cp.async.
// ldmatrix.x4 fragment loads; B reg pairing is (r0,r2)/(r1,r3) for this
// addressing (lanes 0-7: n0-7 | 8-15: n8-15 | 16-23: n0-7 k+8 | 24-31: n8-15 k+8).
// outMode: 0 = fp32 row-major, 1 = fp16 [B][H][S][DK], 2 = same scaled by 1/8*log2e
// ---------------------------------------------------------------------------
#define GKS 72
#define GEMM_SMEM (2 * 2 * 128 * GKS * 2)   // 73728 bytes

__device__ __forceinline__ void f16_gemm_body(const __half* __restrict__ A,
                                              const __half* __restrict__ Bt,
                                              const float* __restrict__ bias,
                                              float* __restrict__ Cf,
                                              __half* __restrict__ Ch,
                                              int outMode)
{
    extern __shared__ __half smh[];
    const uint32_t as_u = smem_u32(smh);                       // [2][128][GKS]
    const uint32_t ws_u = as_u + 2 * 128 * GKS * 2;            // [2][128][GKS]

    const int tid  = threadIdx.x;
    const int lane = tid & 31;
    const int w    = tid >> 5;
    const int wm   = w >> 1;          // 0..3
    const int wn   = w & 1;           // 0..1
    const int g    = lane >> 2;
    const int t    = lane & 3;
    const int bm   = blockIdx.y * 128;
    const int bn   = blockIdx.x * 128;

    float acc[2][8][4];
#pragma unroll
    for (int mt = 0; mt < 2; mt++)
#pragma unroll
        for (int nt = 0; nt < 8; nt++)
#pragma unroll
            for (int c = 0; c < 4; c++) acc[mt][nt][c] = 0.f;

    auto load_chunk = [&](int i) {
        const int st = i & 1;
        const int k0 = i * 64;
        const uint32_t ad = as_u + st * 128 * GKS * 2;
        const uint32_t wd = ws_u + st * 128 * GKS * 2;
#pragma unroll
        for (int j = 0; j < 4; j++) {
            int idx = tid + j * 256;          // 1024 chunks of 16B
            int row = idx >> 3, c = idx & 7;
            cp_async16(ad + (row * GKS + c * 8) * 2,
                       A + (size_t)(bm + row) * D_ + k0 + c * 8);
        }
#pragma unroll
        for (int j = 0; j < 4; j++) {
            int idx = tid + j * 256;
            int row = idx >> 3, c = idx & 7;
            cp_async16(wd + (row * GKS + c * 8) * 2,
                       Bt + (size_t)(bn + row) * D_ + k0 + c * 8);
        }
        CP_COMMIT();
    };

    load_chunk(0);

    for (int i = 0; i < 16; i++) {
        if (i < 15) {
            load_chunk(i + 1);
            asm volatile("cp.async.wait_group 1;" ::: "memory");
        } else {
            asm volatile("cp.async.wait_group 0;" ::: "memory");
        }
        __syncthreads();

        const int st = i & 1;
        const uint32_t a_base = as_u + st * 128 * GKS * 2;
        const uint32_t b_base = ws_u + st * 128 * GKS * 2;

#pragma unroll
        for (int kt = 0; kt < 4; kt++) {
            uint32_t a0[4], a1[4];
            uint32_t arow = a_base +
                ((wm * 32 + (lane & 15)) * GKS + kt * 16 + (lane >> 4) * 8) * 2;
            ldsm_x4(a0[0], a0[1], a0[2], a0[3], arow);
            ldsm_x4(a1[0], a1[1], a1[2], a1[3], arow + 16 * GKS * 2);
#pragma unroll
            for (int ntp = 0; ntp < 4; ntp++) {
                uint32_t r0, r1, r2, r3;
                uint32_t baddr = b_base +
                    ((wn * 64 + ntp * 16 + (lane & 15)) * GKS + kt * 16 + (lane >> 4) * 8) * 2;
                ldsm_x4(r0, r1, r2, r3, baddr);
                // r0=(n0-7,k0-7) r1=(n8-15,k0-7) r2=(n0-7,k8-15) r3=(n8-15,k8-15)
                // -> B pairs: (r0,r2) for n0-7, (r1,r3) for n8-15
                mma_f16(acc[0][2 * ntp],     a0[0], a0[1], a0[2], a0[3], r0, r2);
                mma_f16(acc[0][2 * ntp + 1], a0[0], a0[1], a0[2], a0[3], r1, r3);
                mma_f16(acc[1][2 * ntp],     a1[0], a1[1], a1[2], a1[3], r0, r2);
                mma_f16(acc[1][2 * ntp + 1], a1[0], a1[1], a1[2], a1[3], r1, r3);
            }
        }
        __syncthreads();
    }

    const float qs = (outMode == 2) ? (0.125f * LOG2E) : 1.0f;
#pragma unroll
    for (int mt = 0; mt < 2; mt++) {
#pragma unroll
        for (int half = 0; half < 2; half++) {
            int row = bm + wm * 32 + mt * 16 + g + half * 8;
#pragma unroll
            for (int nt = 0; nt < 8; nt++) {
                int col = bn + wn * 64 + nt * 8 + 2 * t;
                float vx = acc[mt][nt][half * 2 + 0] + bias[col + 0];
                float vy = acc[mt][nt][half * 2 + 1] + bias[col + 1];
                if (outMode == 0) {
                    *(float2*)&Cf[(size_t)row * D_ + col] = make_float2(vx, vy);
                } else {
                    int bb = row >> 11;
                    int ss = row & (S_ - 1);
                    int h  = col >> 6;
                    int dk = col & (DK_ - 1);
                    __half2 hv = __floats2half2_rn(vx * qs, vy * qs);
                    *(__half2*)&Ch[(size_t)(((bb << 4) + h) * S_ + ss) * DK_ + dk] = hv;
                }
            }
        }
    }
}

__global__ void __launch_bounds__(256, 2)
qkv_kernel(const float* __restrict__ bq, const float* __restrict__ bk,
           const float* __restrict__ bv)
{
    const float* bias; __half* dst; const __half* Bt; int mode;
    if (blockIdx.z == 0)      { bias = bq; dst = g_Qh; Bt = g_Wh;                       mode = 2; }
    else if (blockIdx.z == 1) { bias = bk; dst = g_Kh; Bt = g_Wh + (size_t)D_ * D_;     mode = 1; }
    else                      { bias = bv; dst = g_Vh; Bt = g_Wh + (size_t)2 * D_ * D_; mode = 1; }
    f16_gemm_body(g_Xh, Bt, bias, nullptr, dst, mode);
}

__global__ void __launch_bounds__(256, 2)
outproj_kernel(const float* __restrict__ bo, float* __restrict__ out)
{
    f16_gemm_body(g_ctx, g_Wh + (size_t)3 * D_ * D_, bo, out, nullptr, 0);
}

// ---------------------------------------------------------------------------
// fp16 flash attention. Block: 128 q x one (b,h), 8 warps (16 q-rows each).
// KV tiles of 64, cp.async double-buffered, ldmatrix fragments, P in regs,
// base-2 softmax (log2e folded into Q), skip-rescale when max unchanged.
// Smem (half): Qs[128][72], Ks[2][64][72], Vs[2][64][72] = 55296 B
// ---------------------------------------------------------------------------
#define ATS 72
#define ATTN_SMEM ((128 * ATS + 2 * 64 * ATS + 2 * 64 * ATS) * 2)

__global__ void __launch_bounds__(256, 2)
attn_kernel()
{
    extern __shared__ __half smb[];
    const uint32_t qs_u = smem_u32(smb);
    const uint32_t ks_u = qs_u + 128 * ATS * 2;
    const uint32_t vs_u = ks_u + 2 * 64 * ATS * 2;

    const int tid  = threadIdx.x;
    const int lane = tid & 31;
    const int w    = tid >> 5;
    const int g    = lane >> 2;
    const int t    = lane & 3;
    const int wq   = w * 16;

    const int q0 = blockIdx.x * 128;
    const int h  = blockIdx.y;
    const int b  = blockIdx.z;
    const size_t headBase = (size_t)((b * H_) + h) * S_ * DK_;

    // Q tile -> smem (group 0)
#pragma unroll
    for (int j = 0; j < 4; j++) {
        int idx = tid + j * 256;
        int row = idx >> 3, c = idx & 7;
        cp_async16(qs_u + (row * ATS + c * 8) * 2,
                   g_Qh + headBase + (size_t)(q0 + row) * DK_ + c * 8);
    }
    CP_COMMIT();

    auto load_kv = [&](int iter) {
        int st = iter & 1;
        int k0 = iter * 64;
        uint32_t kd = ks_u + st * 64 * ATS * 2;
        uint32_t vd = vs_u + st * 64 * ATS * 2;
#pragma unroll
        for (int j = 0; j < 2; j++) {
            int idx = tid + j * 256;
            int row = idx >> 3, c = idx & 7;
            cp_async16(kd + (row * ATS + c * 8) * 2,
                       g_Kh + headBase + (size_t)(k0 + row) * DK_ + c * 8);
        }
#pragma unroll
        for (int j = 0; j < 2; j++) {
            int idx = tid + j * 256;
            int row = idx >> 3, c = idx & 7;
            cp_async16(vd + (row * ATS + c * 8) * 2,
                       g_Vh + headBase + (size_t)(k0 + row) * DK_ + c * 8);
        }
        CP_COMMIT();
    };
    load_kv(0);

    asm volatile("cp.async.wait_group 1;" ::: "memory");
    __syncthreads();

    uint32_t qa[4][4];
#pragma unroll
    for (int kt = 0; kt < 4; kt++) {
        uint32_t addr = qs_u + ((wq + (lane & 15)) * ATS + kt * 16 + (lane >> 4) * 8) * 2;
        ldsm_x4(qa[kt][0], qa[kt][1], qa[kt][2], qa[kt][3], addr);
    }

    float m0 = -1e30f, m1 = -1e30f, l0 = 0.f, l1 = 0.f;
    float o[8][4];
#pragma unroll
    for (int nt = 0; nt < 8; nt++)
#pragma unroll
        for (int c = 0; c < 4; c++) o[nt][c] = 0.f;

    for (int iter = 0; iter < 32; iter++) {
        if (iter + 1 < 32) {
            load_kv(iter + 1);
            asm volatile("cp.async.wait_group 1;" ::: "memory");
        } else {
            asm volatile("cp.async.wait_group 0;" ::: "memory");
        }
        __syncthreads();

        const int st = iter & 1;
        const uint32_t kb_base = ks_u + st * 64 * ATS * 2;
        const uint32_t vb_base = vs_u + st * 64 * ATS * 2;

        // ---- S = Q @ K^T (base-2 logits) ----
        float s[8][4];
#pragma unroll
        for (int nt = 0; nt < 8; nt++)
#pragma unroll
            for (int c = 0; c < 4; c++) s[nt][c] = 0.f;

#pragma unroll
        for (int kt = 0; kt < 4; kt++) {
#pragma unroll
            for (int ntp = 0; ntp < 4; ntp++) {
                uint32_t r0, r1, r2, r3;
                uint32_t addr = kb_base +
                    ((ntp * 16 + (lane >> 4) * 8 + (lane & 7)) * ATS +
                     kt * 16 + ((lane >> 3) & 1) * 8) * 2;
                ldsm_x4(r0, r1, r2, r3, addr);
                mma_f16(s[2 * ntp],     qa[kt][0], qa[kt][1], qa[kt][2], qa[kt][3], r0, r1);
                mma_f16(s[2 * ntp + 1], qa[kt][0], qa[kt][1], qa[kt][2], qa[kt][3], r2, r3);
            }
        }

        // ---- Online softmax (rows g, g+8), base 2 ----
        float mx0 = -1e30f, mx1 = -1e30f;
#pragma unroll
        for (int nt = 0; nt < 8; nt++) {
            mx0 = fmaxf(mx0, fmaxf(s[nt][0], s[nt][1]));
            mx1 = fmaxf(mx1, fmaxf(s[nt][2], s[nt][3]));
        }
        mx0 = fmaxf(mx0, __shfl_xor_sync(0xffffffffu, mx0, 1));
        mx0 = fmaxf(mx0, __shfl_xor_sync(0xffffffffu, mx0, 2));
        mx1 = fmaxf(mx1, __shfl_xor_sync(0xffffffffu, mx1, 1));
        mx1 = fmaxf(mx1, __shfl_xor_sync(0xffffffffu, mx1, 2));

        float m0n = fmaxf(m0, mx0);
        float m1n = fmaxf(m1, mx1);
        float alpha0 = ex2f(m0 - m0n);
        float alpha1 = ex2f(m1 - m1n);
        m0 = m0n; m1 = m1n;

        uint32_t pf[8][2];
        float sum0 = 0.f, sum1 = 0.f;
#pragma unroll
        for (int nt = 0; nt < 8; nt++) {
            float p00 = ex2f(s[nt][0] - m0);
            float p01 = ex2f(s[nt][1] - m0);
            float p10 = ex2f(s[nt][2] - m1);
            float p11 = ex2f(s[nt][3] - m1);
            sum0 += p00 + p01;
            sum1 += p10 + p11;
            pf[nt][0] = pack_h2(p00, p01);
            pf[nt][1] = pack_h2(p10, p11);
        }
        sum0 += __shfl_xor_sync(0xffffffffu, sum0, 1);
        sum0 += __shfl_xor_sync(0xffffffffu, sum0, 2);
        sum1 += __shfl_xor_sync(0xffffffffu, sum1, 1);
        sum1 += __shfl_xor_sync(0xffffffffu, sum1, 2);
        l0 = l0 * alpha0 + sum0;
        l1 = l1 * alpha1 + sum1;

        // ---- O rescale (skipped when max unchanged), then O += P @ V ----
        if (alpha0 != 1.0f || alpha1 != 1.0f) {
#pragma unroll
            for (int nt = 0; nt < 8; nt++) {
                o[nt][0] *= alpha0; o[nt][1] *= alpha0;
                o[nt][2] *= alpha1; o[nt][3] *= alpha1;
            }
        }

#pragma unroll
        for (int kt = 0; kt < 4; kt++) {
            uint32_t a0 = pf[2 * kt][0];
            uint32_t a1 = pf[2 * kt][1];
            uint32_t a2 = pf[2 * kt + 1][0];
            uint32_t a3 = pf[2 * kt + 1][1];
#pragma unroll
            for (int ntp = 0; ntp < 4; ntp++) {
                uint32_t r0, r1, r2, r3;
                uint32_t addr = vb_base +
                    ((kt * 16 + ((lane >> 3) & 1) * 8 + (lane & 7)) * ATS +
                     ntp * 16 + (lane >> 4) * 8) * 2;
                ldsm_x4_t(r0, r1, r2, r3, addr);
                mma_f16(o[2 * ntp],     a0, a1, a2, a3, r0, r1);
                mma_f16(o[2 * ntp + 1], a0, a1, a2, a3, r2, r3);
            }
        }
        __syncthreads();
    }

    // ---- Normalize and store ctx (fp16) ----
    float inv0 = 1.0f / l0;
    float inv1 = 1.0f / l1;
    int row0 = b * S_ + q0 + wq + g;
    int row1 = row0 + 8;
#pragma unroll
    for (int nt = 0; nt < 8; nt++) {
        int col = h * DK_ + nt * 8 + 2 * t;
        __half2 v0 = __floats2half2_rn(o[nt][0] * inv0, o[nt][1] * inv0);
        __half2 v1 = __floats2half2_rn(o[nt][2] * inv1, o[nt][3] * inv1);
        *(__half2*)&g_ctx[(size_t)row0 * D_ + col] = v0;
        *(__half2*)&g_ctx[(size_t)row1 * D_ + col] = v1;
    }
}

// ---------------------------------------------------------------------------
// Launch
// ---------------------------------------------------------------------------
extern "C" void kernel_launch(void* const* d_in, const int* in_sizes, int n_in,
                              void* d_out, int out_size)
{
    const float* query = (const float*)d_in[0];
    const float* Wq = (const float*)d_in[1];
    const float* bq = (const float*)d_in[2];
    const float* Wk = (const float*)d_in[3];
    const float* bk = (const float*)d_in[4];
    const float* Wv = (const float*)d_in[5];
    const float* bv = (const float*)d_in[6];
    const float* Wo = (const float*)d_in[7];
    const float* bo = (const float*)d_in[8];
    float* out = (float*)d_out;

    cudaFuncSetAttribute(qkv_kernel, cudaFuncAttributeMaxDynamicSharedMemorySize, GEMM_SMEM);
    cudaFuncSetAttribute(outproj_kernel, cudaFuncAttributeMaxDynamicSharedMemorySize, GEMM_SMEM);
    cudaFuncSetAttribute(attn_kernel, cudaFuncAttributeMaxDynamicSharedMemorySize, ATTN_SMEM);

    prep_x_kernel<<<(M_ * D_ / 8) / 256, 256>>>(query);
    prep_w_kernel<<<dim3(32, 32, 4), dim3(32, 8)>>>(Wq, Wk, Wv, Wo);

    qkv_kernel<<<dim3(8, 32, 3), 256, GEMM_SMEM>>>(bq, bk, bv);
    attn_kernel<<<dim3(S_ / 128, H_, B_), 256, ATTN_SMEM>>>();
    outproj_kernel<<<dim3(8, 32), 256, GEMM_SMEM>>>(bo, out);
}

// round 7
// speedup vs baseline: 6.8514x; 1.1127x over previous
#include <cuda_runtime.h>
#include <cuda_fp16.h>
#include <cstdint>

// Problem constants
#define B_   2
#define S_   2048
#define D_   1024
#define H_   16
#define DK_  64
#define M_   (B_ * S_)   // 4096

#define LOG2E 1.4426950408889634f

// ---------------------------------------------------------------------------
// Scratch (device globals)
// ---------------------------------------------------------------------------
__device__ __align__(16) __half g_Xh[M_ * D_];            // fp16 input
__device__ __align__(16) __half g_Wh[4 * D_ * D_];        // [N][K] fp16 weights (q,k,v,o)
__device__ __align__(16) __half g_Qh[B_ * H_ * S_ * DK_]; // Q * (1/8 * log2e)
__device__ __align__(16) __half g_Kh[B_ * H_ * S_ * DK_];
__device__ __align__(16) __half g_Vh[B_ * H_ * S_ * DK_];
__device__ __align__(16) __half g_ctx[M_ * D_];           // attention out, fp16

// ---------------------------------------------------------------------------
// Helpers
// ---------------------------------------------------------------------------
__device__ __forceinline__ uint32_t smem_u32(const void* p) {
    uint32_t a;
    asm("{ .reg .u64 t; cvta.to.shared.u64 t, %1; cvt.u32.u64 %0, t; }"
        : "=r"(a) : "l"(p));
    return a;
}

__device__ __forceinline__ void cp_async16(uint32_t dst, const void* src) {
    asm volatile("cp.async.cg.shared.global [%0], [%1], 16;"
                 :: "r"(dst), "l"(src));
}
#define CP_COMMIT() asm volatile("cp.async.commit_group;" ::: "memory")

__device__ __forceinline__ float ex2f(float x) {
    float r;
    asm("ex2.approx.f32 %0, %1;" : "=f"(r) : "f"(x));
    return r;
}

// packed half2 exp2
__device__ __forceinline__ uint32_t ex2_h2(__half2 x) {
    uint32_t xi = *(uint32_t*)&x, r;
    asm("ex2.approx.f16x2 %0, %1;" : "=r"(r) : "r"(xi));
    return r;
}

// fp16 mma, fp32 accumulate
__device__ __forceinline__ void mma_f16(float* c,
                                        uint32_t a0, uint32_t a1,
                                        uint32_t a2, uint32_t a3,
                                        uint32_t b0, uint32_t b1) {
    asm volatile(
        "mma.sync.aligned.m16n8k16.row.col.f32.f16.f16.f32 "
        "{%0,%1,%2,%3}, {%4,%5,%6,%7}, {%8,%9}, {%0,%1,%2,%3};"
        : "+f"(c[0]), "+f"(c[1]), "+f"(c[2]), "+f"(c[3])
        : "r"(a0), "r"(a1), "r"(a2), "r"(a3), "r"(b0), "r"(b1));
}

__device__ __forceinline__ void ldsm_x4(uint32_t& r0, uint32_t& r1,
                                        uint32_t& r2, uint32_t& r3, uint32_t a) {
    asm volatile("ldmatrix.sync.aligned.m8n8.x4.shared.b16 {%0,%1,%2,%3}, [%4];"
                 : "=r"(r0), "=r"(r1), "=r"(r2), "=r"(r3) : "r"(a));
}
__device__ __forceinline__ void ldsm_x4_t(uint32_t& r0, uint32_t& r1,
                                          uint32_t& r2, uint32_t& r3, uint32_t a) {
    asm volatile("ldmatrix.sync.aligned.m8n8.x4.trans.shared.b16 {%0,%1,%2,%3}, [%4];"
                 : "=r"(r0), "=r"(r1), "=r"(r2), "=r"(r3) : "r"(a));
}

__device__ __forceinline__ uint32_t pack_h2(float lo, float hi) {
    __half2 h = __floats2half2_rn(lo, hi);
    return *(uint32_t*)&h;
}

// ---------------------------------------------------------------------------
// Prep: fp32 -> fp16 input; transpose + fp16 weights to [N][K]
// ---------------------------------------------------------------------------
__global__ void __launch_bounds__(256)
prep_x_kernel(const float* __restrict__ X)
{
    int i = blockIdx.x * 256 + threadIdx.x;   // 8 elems per thread
    float4 v0 = ((const float4*)X)[2 * i];
    float4 v1 = ((const float4*)X)[2 * i + 1];
    uint4 o;
    o.x = pack_h2(v0.x, v0.y);
    o.y = pack_h2(v0.z, v0.w);
    o.z = pack_h2(v1.x, v1.y);
    o.w = pack_h2(v1.z, v1.w);
    ((uint4*)g_Xh)[i] = o;
}

__global__ void __launch_bounds__(256)
prep_w_kernel(const float* __restrict__ Wq, const float* __restrict__ Wk,
              const float* __restrict__ Wv, const float* __restrict__ Wo)
{
    __shared__ float t[32][33];
    int z = blockIdx.z;
    const float* W = (z == 0) ? Wq : (z == 1) ? Wk : (z == 2) ? Wv : Wo;
    __half* out = g_Wh + (size_t)z * D_ * D_;
    int n0 = blockIdx.x * 32;
    int k0 = blockIdx.y * 32;
    int x = threadIdx.x, y0 = threadIdx.y;    // block (32, 8)
#pragma unroll
    for (int dy = 0; dy < 32; dy += 8)
        t[y0 + dy][x] = W[(size_t)(k0 + y0 + dy) * D_ + n0 + x];
    __syncthreads();
#pragma unroll
    for (int dy = 0; dy < 32; dy += 8)
        out[(size_t)(n0 + y0 + dy) * D_ + k0 + x] = __float2half_rn(t[x][y0 + dy]);
}

// ---------------------------------------------------------------------------
// fp16 mma GEMM: C[M x 1024] = A[M x 1024] @ Wt^T + bias
// CTA 128x128, 8 warps, K chunks of 64, 3-stage cp.async, ONE sync per iter
// (order: wait -> sync -> compute -> issue chunk i+2).
// outMode: 0 = fp32 row-major, 1 = fp16 [B][H][S][DK], 2 = same scaled by 1/8*log2e
// ---------------------------------------------------------------------------
#define GKS 72
#define GEMM_SMEM (3 * 2 * 128 * GKS * 2)   // 110592 bytes

__device__ __forceinline__ void f16_gemm_body(const __half* __restrict__ A,
                                              const __half* __restrict__ Bt,
                                              const float* __restrict__ bias,
                                              float* __restrict__ Cf,
                                              __half* __restrict__ Ch,
                                              int outMode)
{
    extern __shared__ __half smh[];
    const uint32_t as_u = smem_u32(smh);                       // [3][128][GKS]
    const uint32_t ws_u = as_u + 3 * 128 * GKS * 2;            // [3][128][GKS]

    const int tid  = threadIdx.x;
    const int lane = tid & 31;
    const int w    = tid >> 5;
    const int wm   = w >> 1;          // 0..3
    const int wn   = w & 1;           // 0..1
    const int g    = lane >> 2;
    const int t    = lane & 3;
    const int bm   = blockIdx.y * 128;
    const int bn   = blockIdx.x * 128;

    float acc[2][8][4];
#pragma unroll
    for (int mt = 0; mt < 2; mt++)
#pragma unroll
        for (int nt = 0; nt < 8; nt++)
#pragma unroll
            for (int c = 0; c < 4; c++) acc[mt][nt][c] = 0.f;

    auto load_chunk = [&](int i) {
        const int st = i % 3;
        const int k0 = i * 64;
        const uint32_t ad = as_u + st * 128 * GKS * 2;
        const uint32_t wd = ws_u + st * 128 * GKS * 2;
#pragma unroll
        for (int j = 0; j < 4; j++) {
            int idx = tid + j * 256;          // 1024 chunks of 16B
            int row = idx >> 3, c = idx & 7;
            cp_async16(ad + (row * GKS + c * 8) * 2,
                       A + (size_t)(bm + row) * D_ + k0 + c * 8);
        }
#pragma unroll
        for (int j = 0; j < 4; j++) {
            int idx = tid + j * 256;
            int row = idx >> 3, c = idx & 7;
            cp_async16(wd + (row * GKS + c * 8) * 2,
                       Bt + (size_t)(bn + row) * D_ + k0 + c * 8);
        }
        CP_COMMIT();
    };

    load_chunk(0);
    load_chunk(1);

    for (int i = 0; i < 16; i++) {
        if (i < 15) {
            asm volatile("cp.async.wait_group 1;" ::: "memory");
        } else {
            asm volatile("cp.async.wait_group 0;" ::: "memory");
        }
        __syncthreads();

        const int st = i % 3;
        const uint32_t a_base = as_u + st * 128 * GKS * 2;
        const uint32_t b_base = ws_u + st * 128 * GKS * 2;

#pragma unroll
        for (int kt = 0; kt < 4; kt++) {
            uint32_t a0[4], a1[4];
            uint32_t arow = a_base +
                ((wm * 32 + (lane & 15)) * GKS + kt * 16 + (lane >> 4) * 8) * 2;
            ldsm_x4(a0[0], a0[1], a0[2], a0[3], arow);
            ldsm_x4(a1[0], a1[1], a1[2], a1[3], arow + 16 * GKS * 2);
#pragma unroll
            for (int ntp = 0; ntp < 4; ntp++) {
                uint32_t r0, r1, r2, r3;
                uint32_t baddr = b_base +
                    ((wn * 64 + ntp * 16 + (lane & 15)) * GKS + kt * 16 + (lane >> 4) * 8) * 2;
                ldsm_x4(r0, r1, r2, r3, baddr);
                // B pairs: (r0,r2) for n0-7, (r1,r3) for n8-15
                mma_f16(acc[0][2 * ntp],     a0[0], a0[1], a0[2], a0[3], r0, r2);
                mma_f16(acc[0][2 * ntp + 1], a0[0], a0[1], a0[2], a0[3], r1, r3);
                mma_f16(acc[1][2 * ntp],     a1[0], a1[1], a1[2], a1[3], r0, r2);
                mma_f16(acc[1][2 * ntp + 1], a1[0], a1[1], a1[2], a1[3], r1, r3);
            }
        }

        if (i + 2 < 16) load_chunk(i + 2);   // after sync: prior readers done
    }

    const float qs = (outMode == 2) ? (0.125f * LOG2E) : 1.0f;
#pragma unroll
    for (int mt = 0; mt < 2; mt++) {
#pragma unroll
        for (int half = 0; half < 2; half++) {
            int row = bm + wm * 32 + mt * 16 + g + half * 8;
#pragma unroll
            for (int nt = 0; nt < 8; nt++) {
                int col = bn + wn * 64 + nt * 8 + 2 * t;
                float vx = acc[mt][nt][half * 2 + 0] + bias[col + 0];
                float vy = acc[mt][nt][half * 2 + 1] + bias[col + 1];
                if (outMode == 0) {
                    *(float2*)&Cf[(size_t)row * D_ + col] = make_float2(vx, vy);
                } else {
                    int bb = row >> 11;
                    int ss = row & (S_ - 1);
                    int h  = col >> 6;
                    int dk = col & (DK_ - 1);
                    __half2 hv = __floats2half2_rn(vx * qs, vy * qs);
                    *(__half2*)&Ch[(size_t)(((bb << 4) + h) * S_ + ss) * DK_ + dk] = hv;
                }
            }
        }
    }
}

__global__ void __launch_bounds__(256, 2)
qkv_kernel(const float* __restrict__ bq, const float* __restrict__ bk,
           const float* __restrict__ bv)
{
    const float* bias; __half* dst; const __half* Bt; int mode;
    if (blockIdx.z == 0)      { bias = bq; dst = g_Qh; Bt = g_Wh;                       mode = 2; }
    else if (blockIdx.z == 1) { bias = bk; dst = g_Kh; Bt = g_Wh + (size_t)D_ * D_;     mode = 1; }
    else                      { bias = bv; dst = g_Vh; Bt = g_Wh + (size_t)2 * D_ * D_; mode = 1; }
    f16_gemm_body(g_Xh, Bt, bias, nullptr, dst, mode);
}

__global__ void __launch_bounds__(256, 2)
outproj_kernel(const float* __restrict__ bo, float* __restrict__ out)
{
    f16_gemm_body(g_ctx, g_Wh + (size_t)3 * D_ * D_, bo, out, nullptr, 0);
}

// ---------------------------------------------------------------------------
// fp16 flash attention. Block: 128 q x one (b,h), 8 warps (16 q-rows each).
// KV tiles of 64, 3-stage cp.async (ONE sync/iter), ldmatrix fragments,
// half2 exp2 softmax, row-sum via mma-with-ones, skip-rescale.
// Smem (half): Qs[128][72], Ks[3][64][72], Vs[3][64][72] = 73728 B
// ---------------------------------------------------------------------------
#define ATS 72
#define ATTN_SMEM ((128 * ATS + 3 * 64 * ATS + 3 * 64 * ATS) * 2)
#define ONES_H2 0x3C003C00u

__global__ void __launch_bounds__(256, 2)
attn_kernel()
{
    extern __shared__ __half smb[];
    const uint32_t qs_u = smem_u32(smb);
    const uint32_t ks_u = qs_u + 128 * ATS * 2;
    const uint32_t vs_u = ks_u + 3 * 64 * ATS * 2;

    const int tid  = threadIdx.x;
    const int lane = tid & 31;
    const int w    = tid >> 5;
    const int g    = lane >> 2;
    const int t    = lane & 3;
    const int wq   = w * 16;

    const int q0 = blockIdx.x * 128;
    const int h  = blockIdx.y;
    const int b  = blockIdx.z;
    const size_t headBase = (size_t)((b * H_) + h) * S_ * DK_;

    // Q tile -> smem (own group)
#pragma unroll
    for (int j = 0; j < 4; j++) {
        int idx = tid + j * 256;
        int row = idx >> 3, c = idx & 7;
        cp_async16(qs_u + (row * ATS + c * 8) * 2,
                   g_Qh + headBase + (size_t)(q0 + row) * DK_ + c * 8);
    }
    CP_COMMIT();

    auto load_kv = [&](int iter) {
        int st = iter % 3;
        int k0 = iter * 64;
        uint32_t kd = ks_u + st * 64 * ATS * 2;
        uint32_t vd = vs_u + st * 64 * ATS * 2;
#pragma unroll
        for (int j = 0; j < 2; j++) {
            int idx = tid + j * 256;
            int row = idx >> 3, c = idx & 7;
            cp_async16(kd + (row * ATS + c * 8) * 2,
                       g_Kh + headBase + (size_t)(k0 + row) * DK_ + c * 8);
        }
#pragma unroll
        for (int j = 0; j < 2; j++) {
            int idx = tid + j * 256;
            int row = idx >> 3, c = idx & 7;
            cp_async16(vd + (row * ATS + c * 8) * 2,
                       g_Vh + headBase + (size_t)(k0 + row) * DK_ + c * 8);
        }
        CP_COMMIT();
    };
    load_kv(0);
    load_kv(1);

    // Q done (kv0, kv1 may be pending); barrier makes all threads' Q visible
    asm volatile("cp.async.wait_group 2;" ::: "memory");
    __syncthreads();

    uint32_t qa[4][4];
#pragma unroll
    for (int kt = 0; kt < 4; kt++) {
        uint32_t addr = qs_u + ((wq + (lane & 15)) * ATS + kt * 16 + (lane >> 4) * 8) * 2;
        ldsm_x4(qa[kt][0], qa[kt][1], qa[kt][2], qa[kt][3], addr);
    }

    float m0 = -1e30f, m1 = -1e30f;
    float lacc[4] = {0.f, 0.f, 0.f, 0.f};   // [0]=row g sum, [2]=row g+8 sum
    float o[8][4];
#pragma unroll
    for (int nt = 0; nt < 8; nt++)
#pragma unroll
        for (int c = 0; c < 4; c++) o[nt][c] = 0.f;

    for (int iter = 0; iter < 32; iter++) {
        if (iter < 31) {
            asm volatile("cp.async.wait_group 1;" ::: "memory");
        } else {
            asm volatile("cp.async.wait_group 0;" ::: "memory");
        }
        __syncthreads();

        const int st = iter % 3;
        const uint32_t kb_base = ks_u + st * 64 * ATS * 2;
        const uint32_t vb_base = vs_u + st * 64 * ATS * 2;

        // ---- S = Q @ K^T (base-2 logits) ----
        float s[8][4];
#pragma unroll
        for (int nt = 0; nt < 8; nt++)
#pragma unroll
            for (int c = 0; c < 4; c++) s[nt][c] = 0.f;

#pragma unroll
        for (int kt = 0; kt < 4; kt++) {
#pragma unroll
            for (int ntp = 0; ntp < 4; ntp++) {
                uint32_t r0, r1, r2, r3;
                uint32_t addr = kb_base +
                    ((ntp * 16 + (lane >> 4) * 8 + (lane & 7)) * ATS +
                     kt * 16 + ((lane >> 3) & 1) * 8) * 2;
                ldsm_x4(r0, r1, r2, r3, addr);
                mma_f16(s[2 * ntp],     qa[kt][0], qa[kt][1], qa[kt][2], qa[kt][3], r0, r1);
                mma_f16(s[2 * ntp + 1], qa[kt][0], qa[kt][1], qa[kt][2], qa[kt][3], r2, r3);
            }
        }

        // ---- Online softmax (rows g, g+8), base 2, half2 exp ----
        float mx0 = -1e30f, mx1 = -1e30f;
#pragma unroll
        for (int nt = 0; nt < 8; nt++) {
            mx0 = fmaxf(mx0, fmaxf(s[nt][0], s[nt][1]));
            mx1 = fmaxf(mx1, fmaxf(s[nt][2], s[nt][3]));
        }
        mx0 = fmaxf(mx0, __shfl_xor_sync(0xffffffffu, mx0, 1));
        mx0 = fmaxf(mx0, __shfl_xor_sync(0xffffffffu, mx0, 2));
        mx1 = fmaxf(mx1, __shfl_xor_sync(0xffffffffu, mx1, 1));
        mx1 = fmaxf(mx1, __shfl_xor_sync(0xffffffffu, mx1, 2));

        float m0n = fmaxf(m0, mx0);
        float m1n = fmaxf(m1, mx1);
        float alpha0 = ex2f(m0 - m0n);
        float alpha1 = ex2f(m1 - m1n);
        m0 = m0n; m1 = m1n;

        __half2 m0h = __floats2half2_rn(m0n, m0n);
        __half2 m1h = __floats2half2_rn(m1n, m1n);
        uint32_t pf[8][2];
#pragma unroll
        for (int nt = 0; nt < 8; nt++) {
            __half2 sh0 = __hsub2(__floats2half2_rn(s[nt][0], s[nt][1]), m0h);
            __half2 sh1 = __hsub2(__floats2half2_rn(s[nt][2], s[nt][3]), m1h);
            pf[nt][0] = ex2_h2(sh0);
            pf[nt][1] = ex2_h2(sh1);
        }

        // ---- rescale O and l (skipped when max unchanged) ----
        if (alpha0 != 1.0f || alpha1 != 1.0f) {
#pragma unroll
            for (int nt = 0; nt < 8; nt++) {
                o[nt][0] *= alpha0; o[nt][1] *= alpha0;
                o[nt][2] *= alpha1; o[nt][3] *= alpha1;
            }
            lacc[0] *= alpha0; lacc[2] *= alpha1;
        }

        // ---- l += rowsum(P) via mma with all-ones B ----
#pragma unroll
        for (int kt = 0; kt < 4; kt++)
            mma_f16(lacc, pf[2 * kt][0], pf[2 * kt][1],
                    pf[2 * kt + 1][0], pf[2 * kt + 1][1], ONES_H2, ONES_H2);

        // ---- O += P @ V ----
#pragma unroll
        for (int kt = 0; kt < 4; kt++) {
            uint32_t a0 = pf[2 * kt][0];
            uint32_t a1 = pf[2 * kt][1];
            uint32_t a2 = pf[2 * kt + 1][0];
            uint32_t a3 = pf[2 * kt + 1][1];
#pragma unroll
            for (int ntp = 0; ntp < 4; ntp++) {
                uint32_t r0, r1, r2, r3;
                uint32_t addr = vb_base +
                    ((kt * 16 + ((lane >> 3) & 1) * 8 + (lane & 7)) * ATS +
                     ntp * 16 + (lane >> 4) * 8) * 2;
                ldsm_x4_t(r0, r1, r2, r3, addr);
                mma_f16(o[2 * ntp],     a0, a1, a2, a3, r0, r1);
                mma_f16(o[2 * ntp + 1], a0, a1, a2, a3, r2, r3);
            }
        }

        if (iter + 2 < 32) load_kv(iter + 2);   // after sync: prior readers done
    }

    // ---- Normalize and store ctx (fp16) ----
    float inv0 = 1.0f / lacc[0];
    float inv1 = 1.0f / lacc[2];
    int row0 = b * S_ + q0 + wq + g;
    int row1 = row0 + 8;
#pragma unroll
    for (int nt = 0; nt < 8; nt++) {
        int col = h * DK_ + nt * 8 + 2 * t;
        __half2 v0 = __floats2half2_rn(o[nt][0] * inv0, o[nt][1] * inv0);
        __half2 v1 = __floats2half2_rn(o[nt][2] * inv1, o[nt][3] * inv1);
        *(__half2*)&g_ctx[(size_t)row0 * D_ + col] = v0;
        *(__half2*)&g_ctx[(size_t)row1 * D_ + col] = v1;
    }
}

// ---------------------------------------------------------------------------
// Launch
// ---------------------------------------------------------------------------
extern "C" void kernel_launch(void* const* d_in, const int* in_sizes, int n_in,
                              void* d_out, int out_size)
{
    const float* query = (const float*)d_in[0];
    const float* Wq = (const float*)d_in[1];
    const float* bq = (const float*)d_in[2];
    const float* Wk = (const float*)d_in[3];
    const float* bk = (const float*)d_in[4];
    const float* Wv = (const float*)d_in[5];
    const float* bv = (const float*)d_in[6];
    const float* Wo = (const float*)d_in[7];
    const float* bo = (const float*)d_in[8];
    float* out = (float*)d_out;

    cudaFuncSetAttribute(qkv_kernel, cudaFuncAttributeMaxDynamicSharedMemorySize, GEMM_SMEM);
    cudaFuncSetAttribute(outproj_kernel, cudaFuncAttributeMaxDynamicSharedMemorySize, GEMM_SMEM);
    cudaFuncSetAttribute(attn_kernel, cudaFuncAttributeMaxDynamicSharedMemorySize, ATTN_SMEM);

    prep_x_kernel<<<(M_ * D_ / 8) / 256, 256>>>(query);
    prep_w_kernel<<<dim3(32, 32, 4), dim3(32, 8)>>>(Wq, Wk, Wv, Wo);

    qkv_kernel<<<dim3(8, 32, 3), 256, GEMM_SMEM>>>(bq, bk, bv);
    attn_kernel<<<dim3(S_ / 128, H_, B_), 256, ATTN_SMEM>>>();
    outproj_kernel<<<dim3(8, 32), 256, GEMM_SMEM>>>(bo, out);
}

// round 8
// speedup vs baseline: 6.8721x; 1.0030x over previous
#include <cuda_runtime.h>
#include <cuda_fp16.h>
#include <cstdint>

// Problem constants
#define B_   2
#define S_   2048
#define D_   1024
#define H_   16
#define DK_  64
#define M_   (B_ * S_)   // 4096

#define LOG2E 1.4426950408889634f

// ---------------------------------------------------------------------------
// Scratch (device globals)
// ---------------------------------------------------------------------------
__device__ __align__(16) __half g_Xh[M_ * D_];            // fp16 input
__device__ __align__(16) __half g_Wh[4 * D_ * D_];        // [N][K] fp16 weights (q,k,v,o)
__device__ __align__(16) __half g_Qh[B_ * H_ * S_ * DK_]; // Q * (1/8 * log2e)
__device__ __align__(16) __half g_Kh[B_ * H_ * S_ * DK_];
__device__ __align__(16) __half g_Vh[B_ * H_ * S_ * DK_];
__device__ __align__(16) __half g_ctx[M_ * D_];           // attention out, fp16

// ---------------------------------------------------------------------------
// Helpers
// ---------------------------------------------------------------------------
__device__ __forceinline__ uint32_t smem_u32(const void* p) {
    uint32_t a;
    asm("{ .reg .u64 t; cvta.to.shared.u64 t, %1; cvt.u32.u64 %0, t; }"
        : "=r"(a) : "l"(p));
    return a;
}

__device__ __forceinline__ void cp_async16(uint32_t dst, const void* src) {
    asm volatile("cp.async.cg.shared.global [%0], [%1], 16;"
                 :: "r"(dst), "l"(src));
}
#define CP_COMMIT() asm volatile("cp.async.commit_group;" ::: "memory")

__device__ __forceinline__ float ex2f(float x) {
    float r;
    asm("ex2.approx.f32 %0, %1;" : "=f"(r) : "f"(x));
    return r;
}

// packed half2 exp2
__device__ __forceinline__ uint32_t ex2_h2(__half2 x) {
    uint32_t xi = *(uint32_t*)&x, r;
    asm("ex2.approx.f16x2 %0, %1;" : "=r"(r) : "r"(xi));
    return r;
}

// fp16 mma, fp32 accumulate
__device__ __forceinline__ void mma_f16(float* c,
                                        uint32_t a0, uint32_t a1,
                                        uint32_t a2, uint32_t a3,
                                        uint32_t b0, uint32_t b1) {
    asm volatile(
        "mma.sync.aligned.m16n8k16.row.col.f32.f16.f16.f32 "
        "{%0,%1,%2,%3}, {%4,%5,%6,%7}, {%8,%9}, {%0,%1,%2,%3};"
        : "+f"(c[0]), "+f"(c[1]), "+f"(c[2]), "+f"(c[3])
        : "r"(a0), "r"(a1), "r"(a2), "r"(a3), "r"(b0), "r"(b1));
}

__device__ __forceinline__ void ldsm_x4(uint32_t& r0, uint32_t& r1,
                                        uint32_t& r2, uint32_t& r3, uint32_t a) {
    asm volatile("ldmatrix.sync.aligned.m8n8.x4.shared.b16 {%0,%1,%2,%3}, [%4];"
                 : "=r"(r0), "=r"(r1), "=r"(r2), "=r"(r3) : "r"(a));
}
__device__ __forceinline__ void ldsm_x4_t(uint32_t& r0, uint32_t& r1,
                                          uint32_t& r2, uint32_t& r3, uint32_t a) {
    asm volatile("ldmatrix.sync.aligned.m8n8.x4.trans.shared.b16 {%0,%1,%2,%3}, [%4];"
                 : "=r"(r0), "=r"(r1), "=r"(r2), "=r"(r3) : "r"(a));
}

__device__ __forceinline__ uint32_t pack_h2(float lo, float hi) {
    __half2 h = __floats2half2_rn(lo, hi);
    return *(uint32_t*)&h;
}

// ---------------------------------------------------------------------------
// Merged prep: z=0..3 -> weight transpose+convert to [N][K] fp16;
//              z=4..5 -> input fp32->fp16 convert.
// grid (32, 32, 6), block (32, 8)
// ---------------------------------------------------------------------------
__global__ void __launch_bounds__(256)
prep_kernel(const float* __restrict__ X,
            const float* __restrict__ Wq, const float* __restrict__ Wk,
            const float* __restrict__ Wv, const float* __restrict__ Wo)
{
    const int z = blockIdx.z;
    if (z < 4) {
        __shared__ float t[32][33];
        const float* W = (z == 0) ? Wq : (z == 1) ? Wk : (z == 2) ? Wv : Wo;
        __half* out = g_Wh + (size_t)z * D_ * D_;
        int n0 = blockIdx.x * 32;
        int k0 = blockIdx.y * 32;
        int x = threadIdx.x, y0 = threadIdx.y;
#pragma unroll
        for (int dy = 0; dy < 32; dy += 8)
            t[y0 + dy][x] = W[(size_t)(k0 + y0 + dy) * D_ + n0 + x];
        __syncthreads();
#pragma unroll
        for (int dy = 0; dy < 32; dy += 8)
            out[(size_t)(n0 + y0 + dy) * D_ + k0 + x] = __float2half_rn(t[x][y0 + dy]);
    } else {
        int tid = threadIdx.y * 32 + threadIdx.x;
        int i = ((z - 4) * 1024 + blockIdx.y * 32 + blockIdx.x) * 256 + tid;
        // 8 elems per thread; 2*1024*256*8 = 4M = M_*D_ exactly
        float4 v0 = ((const float4*)X)[2 * i];
        float4 v1 = ((const float4*)X)[2 * i + 1];
        uint4 o;
        o.x = pack_h2(v0.x, v0.y);
        o.y = pack_h2(v0.z, v0.w);
        o.z = pack_h2(v1.x, v1.y);
        o.w = pack_h2(v1.z, v1.w);
        ((uint4*)g_Xh)[i] = o;
    }
}

// ---------------------------------------------------------------------------
// fp16 mma GEMM: C[M x 1024] = A[M x 1024] @ Wt^T + bias
// CTA 128x128, 8 warps, K chunks of 64, 3-stage cp.async, ONE sync per iter.
// outMode: 0 = fp32 row-major, 1 = fp16 [B][H][S][DK], 2 = same scaled by 1/8*log2e
// ---------------------------------------------------------------------------
#define GKS 72
#define GEMM_SMEM (3 * 2 * 128 * GKS * 2)   // 110592 bytes

__device__ __forceinline__ void f16_gemm_body(const __half* __restrict__ A,
                                              const __half* __restrict__ Bt,
                                              const float* __restrict__ bias,
                                              float* __restrict__ Cf,
                                              __half* __restrict__ Ch,
                                              int outMode)
{
    extern __shared__ __half smh[];
    const uint32_t as_u = smem_u32(smh);                       // [3][128][GKS]
    const uint32_t ws_u = as_u + 3 * 128 * GKS * 2;            // [3][128][GKS]

    const int tid  = threadIdx.x;
    const int lane = tid & 31;
    const int w    = tid >> 5;
    const int wm   = w >> 1;          // 0..3
    const int wn   = w & 1;           // 0..1
    const int g    = lane >> 2;
    const int t    = lane & 3;
    const int bm   = blockIdx.y * 128;
    const int bn   = blockIdx.x * 128;

    float acc[2][8][4];
#pragma unroll
    for (int mt = 0; mt < 2; mt++)
#pragma unroll
        for (int nt = 0; nt < 8; nt++)
#pragma unroll
            for (int c = 0; c < 4; c++) acc[mt][nt][c] = 0.f;

    auto load_chunk = [&](int i) {
        const int st = i % 3;
        const int k0 = i * 64;
        const uint32_t ad = as_u + st * 128 * GKS * 2;
        const uint32_t wd = ws_u + st * 128 * GKS * 2;
#pragma unroll
        for (int j = 0; j < 4; j++) {
            int idx = tid + j * 256;          // 1024 chunks of 16B
            int row = idx >> 3, c = idx & 7;
            cp_async16(ad + (row * GKS + c * 8) * 2,
                       A + (size_t)(bm + row) * D_ + k0 + c * 8);
        }
#pragma unroll
        for (int j = 0; j < 4; j++) {
            int idx = tid + j * 256;
            int row = idx >> 3, c = idx & 7;
            cp_async16(wd + (row * GKS + c * 8) * 2,
                       Bt + (size_t)(bn + row) * D_ + k0 + c * 8);
        }
        CP_COMMIT();
    };

    load_chunk(0);
    load_chunk(1);

    for (int i = 0; i < 16; i++) {
        if (i < 15) {
            asm volatile("cp.async.wait_group 1;" ::: "memory");
        } else {
            asm volatile("cp.async.wait_group 0;" ::: "memory");
        }
        __syncthreads();

        const int st = i % 3;
        const uint32_t a_base = as_u + st * 128 * GKS * 2;
        const uint32_t b_base = ws_u + st * 128 * GKS * 2;

#pragma unroll
        for (int kt = 0; kt < 4; kt++) {
            uint32_t a0[4], a1[4];
            uint32_t arow = a_base +
                ((wm * 32 + (lane & 15)) * GKS + kt * 16 + (lane >> 4) * 8) * 2;
            ldsm_x4(a0[0], a0[1], a0[2], a0[3], arow);
            ldsm_x4(a1[0], a1[1], a1[2], a1[3], arow + 16 * GKS * 2);
#pragma unroll
            for (int ntp = 0; ntp < 4; ntp++) {
                uint32_t r0, r1, r2, r3;
                uint32_t baddr = b_base +
                    ((wn * 64 + ntp * 16 + (lane & 15)) * GKS + kt * 16 + (lane >> 4) * 8) * 2;
                ldsm_x4(r0, r1, r2, r3, baddr);
                // B pairs: (r0,r2) for n0-7, (r1,r3) for n8-15
                mma_f16(acc[0][2 * ntp],     a0[0], a0[1], a0[2], a0[3], r0, r2);
                mma_f16(acc[0][2 * ntp + 1], a0[0], a0[1], a0[2], a0[3], r1, r3);
                mma_f16(acc[1][2 * ntp],     a1[0], a1[1], a1[2], a1[3], r0, r2);
                mma_f16(acc[1][2 * ntp + 1], a1[0], a1[1], a1[2], a1[3], r1, r3);
            }
        }

        if (i + 2 < 16) load_chunk(i + 2);   // after sync: prior readers done
    }

    const float qs = (outMode == 2) ? (0.125f * LOG2E) : 1.0f;
#pragma unroll
    for (int mt = 0; mt < 2; mt++) {
#pragma unroll
        for (int half = 0; half < 2; half++) {
            int row = bm + wm * 32 + mt * 16 + g + half * 8;
#pragma unroll
            for (int nt = 0; nt < 8; nt++) {
                int col = bn + wn * 64 + nt * 8 + 2 * t;
                float vx = acc[mt][nt][half * 2 + 0] + bias[col + 0];
                float vy = acc[mt][nt][half * 2 + 1] + bias[col + 1];
                if (outMode == 0) {
                    *(float2*)&Cf[(size_t)row * D_ + col] = make_float2(vx, vy);
                } else {
                    int bb = row >> 11;
                    int ss = row & (S_ - 1);
                    int h  = col >> 6;
                    int dk = col & (DK_ - 1);
                    __half2 hv = __floats2half2_rn(vx * qs, vy * qs);
                    *(__half2*)&Ch[(size_t)(((bb << 4) + h) * S_ + ss) * DK_ + dk] = hv;
                }
            }
        }
    }
}

__global__ void __launch_bounds__(256, 2)
qkv_kernel(const float* __restrict__ bq, const float* __restrict__ bk,
           const float* __restrict__ bv)
{
    const float* bias; __half* dst; const __half* Bt; int mode;
    if (blockIdx.z == 0)      { bias = bq; dst = g_Qh; Bt = g_Wh;                       mode = 2; }
    else if (blockIdx.z == 1) { bias = bk; dst = g_Kh; Bt = g_Wh + (size_t)D_ * D_;     mode = 1; }
    else                      { bias = bv; dst = g_Vh; Bt = g_Wh + (size_t)2 * D_ * D_; mode = 1; }
    f16_gemm_body(g_Xh, Bt, bias, nullptr, dst, mode);
}

__global__ void __launch_bounds__(256, 2)
outproj_kernel(const float* __restrict__ bo, float* __restrict__ out)
{
    f16_gemm_body(g_ctx, g_Wh + (size_t)3 * D_ * D_, bo, out, nullptr, 0);
}

// ---------------------------------------------------------------------------
// fp16 flash attention. Block: 128 q x one (b,h), 8 warps (16 q-rows each).
// KV tiles of 64, 3-stage cp.async (ONE sync/iter), ldmatrix fragments,
// half2 exp2 softmax, rowsum via HADD2 (off the tensor pipe), skip-rescale.
// Smem (half): Qs[128][72], Ks[3][64][72], Vs[3][64][72] = 73728 B
// ---------------------------------------------------------------------------
#define ATS 72
#define ATTN_SMEM ((128 * ATS + 3 * 64 * ATS + 3 * 64 * ATS) * 2)

__global__ void __launch_bounds__(256, 2)
attn_kernel()
{
    extern __shared__ __half smb[];
    const uint32_t qs_u = smem_u32(smb);
    const uint32_t ks_u = qs_u + 128 * ATS * 2;
    const uint32_t vs_u = ks_u + 3 * 64 * ATS * 2;

    const int tid  = threadIdx.x;
    const int lane = tid & 31;
    const int w    = tid >> 5;
    const int g    = lane >> 2;
    const int t    = lane & 3;
    const int wq   = w * 16;

    const int q0 = blockIdx.x * 128;
    const int h  = blockIdx.y;
    const int b  = blockIdx.z;
    const size_t headBase = (size_t)((b * H_) + h) * S_ * DK_;

    // Q tile -> smem (own group)
#pragma unroll
    for (int j = 0; j < 4; j++) {
        int idx = tid + j * 256;
        int row = idx >> 3, c = idx & 7;
        cp_async16(qs_u + (row * ATS + c * 8) * 2,
                   g_Qh + headBase + (size_t)(q0 + row) * DK_ + c * 8);
    }
    CP_COMMIT();

    auto load_kv = [&](int iter) {
        int st = iter % 3;
        int k0 = iter * 64;
        uint32_t kd = ks_u + st * 64 * ATS * 2;
        uint32_t vd = vs_u + st * 64 * ATS * 2;
#pragma unroll
        for (int j = 0; j < 2; j++) {
            int idx = tid + j * 256;
            int row = idx >> 3, c = idx & 7;
            cp_async16(kd + (row * ATS + c * 8) * 2,
                       g_Kh + headBase + (size_t)(k0 + row) * DK_ + c * 8);
        }
#pragma unroll
        for (int j = 0; j < 2; j++) {
            int idx = tid + j * 256;
            int row = idx >> 3, c = idx & 7;
            cp_async16(vd + (row * ATS + c * 8) * 2,
                       g_Vh + headBase + (size_t)(k0 + row) * DK_ + c * 8);
        }
        CP_COMMIT();
    };
    load_kv(0);
    load_kv(1);

    asm volatile("cp.async.wait_group 2;" ::: "memory");
    __syncthreads();

    uint32_t qa[4][4];
#pragma unroll
    for (int kt = 0; kt < 4; kt++) {
        uint32_t addr = qs_u + ((wq + (lane & 15)) * ATS + kt * 16 + (lane >> 4) * 8) * 2;
        ldsm_x4(qa[kt][0], qa[kt][1], qa[kt][2], qa[kt][3], addr);
    }

    float m0 = -1e30f, m1 = -1e30f, l0 = 0.f, l1 = 0.f;
    float o[8][4];
#pragma unroll
    for (int nt = 0; nt < 8; nt++)
#pragma unroll
        for (int c = 0; c < 4; c++) o[nt][c] = 0.f;

    for (int iter = 0; iter < 32; iter++) {
        if (iter < 31) {
            asm volatile("cp.async.wait_group 1;" ::: "memory");
        } else {
            asm volatile("cp.async.wait_group 0;" ::: "memory");
        }
        __syncthreads();

        const int st = iter % 3;
        const uint32_t kb_base = ks_u + st * 64 * ATS * 2;
        const uint32_t vb_base = vs_u + st * 64 * ATS * 2;

        // ---- S = Q @ K^T (base-2 logits) ----
        float s[8][4];
#pragma unroll
        for (int nt = 0; nt < 8; nt++)
#pragma unroll
            for (int c = 0; c < 4; c++) s[nt][c] = 0.f;

#pragma unroll
        for (int kt = 0; kt < 4; kt++) {
#pragma unroll
            for (int ntp = 0; ntp < 4; ntp++) {
                uint32_t r0, r1, r2, r3;
                uint32_t addr = kb_base +
                    ((ntp * 16 + (lane >> 4) * 8 + (lane & 7)) * ATS +
                     kt * 16 + ((lane >> 3) & 1) * 8) * 2;
                ldsm_x4(r0, r1, r2, r3, addr);
                mma_f16(s[2 * ntp],     qa[kt][0], qa[kt][1], qa[kt][2], qa[kt][3], r0, r1);
                mma_f16(s[2 * ntp + 1], qa[kt][0], qa[kt][1], qa[kt][2], qa[kt][3], r2, r3);
            }
        }

        // ---- Online softmax (rows g, g+8), base 2, half2 exp ----
        float mx0 = -1e30f, mx1 = -1e30f;
#pragma unroll
        for (int nt = 0; nt < 8; nt++) {
            mx0 = fmaxf(mx0, fmaxf(s[nt][0], s[nt][1]));
            mx1 = fmaxf(mx1, fmaxf(s[nt][2], s[nt][3]));
        }
        mx0 = fmaxf(mx0, __shfl_xor_sync(0xffffffffu, mx0, 1));
        mx0 = fmaxf(mx0, __shfl_xor_sync(0xffffffffu, mx0, 2));
        mx1 = fmaxf(mx1, __shfl_xor_sync(0xffffffffu, mx1, 1));
        mx1 = fmaxf(mx1, __shfl_xor_sync(0xffffffffu, mx1, 2));

        float m0n = fmaxf(m0, mx0);
        float m1n = fmaxf(m1, mx1);
        float alpha0 = ex2f(m0 - m0n);
        float alpha1 = ex2f(m1 - m1n);
        m0 = m0n; m1 = m1n;

        __half2 m0h = __floats2half2_rn(m0n, m0n);
        __half2 m1h = __floats2half2_rn(m1n, m1n);
        uint32_t pf[8][2];
#pragma unroll
        for (int nt = 0; nt < 8; nt++) {
            __half2 sh0 = __hsub2(__floats2half2_rn(s[nt][0], s[nt][1]), m0h);
            __half2 sh1 = __hsub2(__floats2half2_rn(s[nt][2], s[nt][3]), m1h);
            pf[nt][0] = ex2_h2(sh0);
            pf[nt][1] = ex2_h2(sh1);
        }

        // ---- rescale O and l (skipped when max unchanged) ----
        if (alpha0 != 1.0f || alpha1 != 1.0f) {
#pragma unroll
            for (int nt = 0; nt < 8; nt++) {
                o[nt][0] *= alpha0; o[nt][1] *= alpha0;
                o[nt][2] *= alpha1; o[nt][3] *= alpha1;
            }
            l0 *= alpha0; l1 *= alpha1;
        }

        // ---- l += rowsum(P) via HADD2 (keeps tensor pipe free) ----
        {
            __half2 a0 = *(__half2*)&pf[0][0];
            __half2 a1 = *(__half2*)&pf[0][1];
#pragma unroll
            for (int nt = 1; nt < 8; nt++) {
                a0 = __hadd2(a0, *(__half2*)&pf[nt][0]);
                a1 = __hadd2(a1, *(__half2*)&pf[nt][1]);
            }
            float sum0 = __low2float(a0) + __high2float(a0);
            float sum1 = __low2float(a1) + __high2float(a1);
            sum0 += __shfl_xor_sync(0xffffffffu, sum0, 1);
            sum0 += __shfl_xor_sync(0xffffffffu, sum0, 2);
            sum1 += __shfl_xor_sync(0xffffffffu, sum1, 1);
            sum1 += __shfl_xor_sync(0xffffffffu, sum1, 2);
            l0 += sum0;
            l1 += sum1;
        }

        // ---- O += P @ V ----
#pragma unroll
        for (int kt = 0; kt < 4; kt++) {
            uint32_t a0 = pf[2 * kt][0];
            uint32_t a1 = pf[2 * kt][1];
            uint32_t a2 = pf[2 * kt + 1][0];
            uint32_t a3 = pf[2 * kt + 1][1];
#pragma unroll
            for (int ntp = 0; ntp < 4; ntp++) {
                uint32_t r0, r1, r2, r3;
                uint32_t addr = vb_base +
                    ((kt * 16 + ((lane >> 3) & 1) * 8 + (lane & 7)) * ATS +
                     ntp * 16 + (lane >> 4) * 8) * 2;
                ldsm_x4_t(r0, r1, r2, r3, addr);
                mma_f16(o[2 * ntp],     a0, a1, a2, a3, r0, r1);
                mma_f16(o[2 * ntp + 1], a0, a1, a2, a3, r2, r3);
            }
        }

        if (iter + 2 < 32) load_kv(iter + 2);
    }

    // ---- Normalize and store ctx (fp16) ----
    float inv0 = 1.0f / l0;
    float inv1 = 1.0f / l1;
    int row0 = b * S_ + q0 + wq + g;
    int row1 = row0 + 8;
#pragma unroll
    for (int nt = 0; nt < 8; nt++) {
        int col = h * DK_ + nt * 8 + 2 * t;
        __half2 v0 = __floats2half2_rn(o[nt][0] * inv0, o[nt][1] * inv0);
        __half2 v1 = __floats2half2_rn(o[nt][2] * inv1, o[nt][3] * inv1);
        *(__half2*)&g_ctx[(size_t)row0 * D_ + col] = v0;
        *(__half2*)&g_ctx[(size_t)row1 * D_ + col] = v1;
    }
}

// ---------------------------------------------------------------------------
// Launch
// ---------------------------------------------------------------------------
extern "C" void kernel_launch(void* const* d_in, const int* in_sizes, int n_in,
                              void* d_out, int out_size)
{
    const float* query = (const float*)d_in[0];
    const float* Wq = (const float*)d_in[1];
    const float* bq = (const float*)d_in[2];
    const float* Wk = (const float*)d_in[3];
    const float* bk = (const float*)d_in[4];
    const float* Wv = (const float*)d_in[5];
    const float* bv = (const float*)d_in[6];
    const float* Wo = (const float*)d_in[7];
    const float* bo = (const float*)d_in[8];
    float* out = (float*)d_out;

    cudaFuncSetAttribute(qkv_kernel, cudaFuncAttributeMaxDynamicSharedMemorySize, GEMM_SMEM);
    cudaFuncSetAttribute(outproj_kernel, cudaFuncAttributeMaxDynamicSharedMemorySize, GEMM_SMEM);
    cudaFuncSetAttribute(attn_kernel, cudaFuncAttributeMaxDynamicSharedMemorySize, ATTN_SMEM);

    prep_kernel<<<dim3(32, 32, 6), dim3(32, 8)>>>(query, Wq, Wk, Wv, Wo);

    qkv_kernel<<<dim3(8, 32, 3), 256, GEMM_SMEM>>>(bq, bk, bv);
    attn_kernel<<<dim3(S_ / 128, H_, B_), 256, ATTN_SMEM>>>();
    outproj_kernel<<<dim3(8, 32), 256, GEMM_SMEM>>>(bo, out);
}

// round 9
// speedup vs baseline: 7.0892x; 1.0316x over previous
#include <cuda_runtime.h>
#include <cuda_fp16.h>
#include <cstdint>

// Problem constants
#define B_   2
#define S_   2048
#define D_   1024
#define H_   16
#define DK_  64
#define M_   (B_ * S_)   // 4096

#define LOG2E 1.4426950408889634f

// ---------------------------------------------------------------------------
// Scratch (device globals)
// ---------------------------------------------------------------------------
__device__ __align__(16) __half g_Xh[M_ * D_];            // fp16 input
__device__ __align__(16) __half g_Wh[4 * D_ * D_];        // [N][K] fp16 weights (q,k,v,o)
__device__ __align__(16) __half g_Qh[B_ * H_ * S_ * DK_]; // Q * (1/8 * log2e)
__device__ __align__(16) __half g_Kh[B_ * H_ * S_ * DK_];
__device__ __align__(16) __half g_Vh[B_ * H_ * S_ * DK_];
__device__ __align__(16) __half g_ctx[M_ * D_];           // attention out, fp16

// ---------------------------------------------------------------------------
// Helpers
// ---------------------------------------------------------------------------
__device__ __forceinline__ uint32_t smem_u32(const void* p) {
    uint32_t a;
    asm("{ .reg .u64 t; cvta.to.shared.u64 t, %1; cvt.u32.u64 %0, t; }"
        : "=r"(a) : "l"(p));
    return a;
}

__device__ __forceinline__ void cp_async16(uint32_t dst, const void* src) {
    asm volatile("cp.async.cg.shared.global [%0], [%1], 16;"
                 :: "r"(dst), "l"(src));
}
#define CP_COMMIT() asm volatile("cp.async.commit_group;" ::: "memory")

__device__ __forceinline__ float ex2f(float x) {
    float r;
    asm("ex2.approx.f32 %0, %1;" : "=f"(r) : "f"(x));
    return r;
}

// packed half2 exp2
__device__ __forceinline__ uint32_t ex2_h2(__half2 x) {
    uint32_t xi = *(uint32_t*)&x, r;
    asm("ex2.approx.f16x2 %0, %1;" : "=r"(r) : "r"(xi));
    return r;
}

// fp16 mma, fp32 accumulate
__device__ __forceinline__ void mma_f16(float* c,
                                        uint32_t a0, uint32_t a1,
                                        uint32_t a2, uint32_t a3,
                                        uint32_t b0, uint32_t b1) {
    asm volatile(
        "mma.sync.aligned.m16n8k16.row.col.f32.f16.f16.f32 "
        "{%0,%1,%2,%3}, {%4,%5,%6,%7}, {%8,%9}, {%0,%1,%2,%3};"
        : "+f"(c[0]), "+f"(c[1]), "+f"(c[2]), "+f"(c[3])
        : "r"(a0), "r"(a1), "r"(a2), "r"(a3), "r"(b0), "r"(b1));
}

__device__ __forceinline__ void ldsm_x4(uint32_t& r0, uint32_t& r1,
                                        uint32_t& r2, uint32_t& r3, uint32_t a) {
    asm volatile("ldmatrix.sync.aligned.m8n8.x4.shared.b16 {%0,%1,%2,%3}, [%4];"
                 : "=r"(r0), "=r"(r1), "=r"(r2), "=r"(r3) : "r"(a));
}
__device__ __forceinline__ void ldsm_x4_t(uint32_t& r0, uint32_t& r1,
                                          uint32_t& r2, uint32_t& r3, uint32_t a) {
    asm volatile("ldmatrix.sync.aligned.m8n8.x4.trans.shared.b16 {%0,%1,%2,%3}, [%4];"
                 : "=r"(r0), "=r"(r1), "=r"(r2), "=r"(r3) : "r"(a));
}

__device__ __forceinline__ uint32_t pack_h2(float lo, float hi) {
    __half2 h = __floats2half2_rn(lo, hi);
    return *(uint32_t*)&h;
}

// ---------------------------------------------------------------------------
// Merged prep: z=0..3 -> weight transpose+convert to [N][K] fp16;
//              z=4..5 -> input fp32->fp16 convert.
// grid (32, 32, 6), block (32, 8)
// ---------------------------------------------------------------------------
__global__ void __launch_bounds__(256)
prep_kernel(const float* __restrict__ X,
            const float* __restrict__ Wq, const float* __restrict__ Wk,
            const float* __restrict__ Wv, const float* __restrict__ Wo)
{
    const int z = blockIdx.z;
    if (z < 4) {
        __shared__ float t[32][33];
        const float* W = (z == 0) ? Wq : (z == 1) ? Wk : (z == 2) ? Wv : Wo;
        __half* out = g_Wh + (size_t)z * D_ * D_;
        int n0 = blockIdx.x * 32;
        int k0 = blockIdx.y * 32;
        int x = threadIdx.x, y0 = threadIdx.y;
#pragma unroll
        for (int dy = 0; dy < 32; dy += 8)
            t[y0 + dy][x] = W[(size_t)(k0 + y0 + dy) * D_ + n0 + x];
        __syncthreads();
#pragma unroll
        for (int dy = 0; dy < 32; dy += 8)
            out[(size_t)(n0 + y0 + dy) * D_ + k0 + x] = __float2half_rn(t[x][y0 + dy]);
    } else {
        int tid = threadIdx.y * 32 + threadIdx.x;
        int i = ((z - 4) * 1024 + blockIdx.y * 32 + blockIdx.x) * 256 + tid;
        float4 v0 = ((const float4*)X)[2 * i];
        float4 v1 = ((const float4*)X)[2 * i + 1];
        uint4 o;
        o.x = pack_h2(v0.x, v0.y);
        o.y = pack_h2(v0.z, v0.w);
        o.z = pack_h2(v1.x, v1.y);
        o.w = pack_h2(v1.z, v1.w);
        ((uint4*)g_Xh)[i] = o;
    }
}

// ---------------------------------------------------------------------------
// fp16 mma GEMM: C[M x 1024] = A[M x 1024] @ Wt^T + bias
// CTA 128x128, 8 warps, K chunks of 64, 3-stage cp.async, ONE sync per iter.
// outMode: 0 = fp32 row-major, 1 = fp16 [B][H][S][DK], 2 = same scaled by 1/8*log2e
// ---------------------------------------------------------------------------
#define GKS 72
#define GEMM_SMEM (3 * 2 * 128 * GKS * 2)   // 110592 bytes

__device__ __forceinline__ void f16_gemm_body(const __half* __restrict__ A,
                                              const __half* __restrict__ Bt,
                                              const float* __restrict__ bias,
                                              float* __restrict__ Cf,
                                              __half* __restrict__ Ch,
                                              int outMode)
{
    extern __shared__ __half smh[];
    const uint32_t as_u = smem_u32(smh);                       // [3][128][GKS]
    const uint32_t ws_u = as_u + 3 * 128 * GKS * 2;            // [3][128][GKS]

    const int tid  = threadIdx.x;
    const int lane = tid & 31;
    const int w    = tid >> 5;
    const int wm   = w >> 1;          // 0..3
    const int wn   = w & 1;           // 0..1
    const int g    = lane >> 2;
    const int t    = lane & 3;
    const int bm   = blockIdx.y * 128;
    const int bn   = blockIdx.x * 128;

    float acc[2][8][4];
#pragma unroll
    for (int mt = 0; mt < 2; mt++)
#pragma unroll
        for (int nt = 0; nt < 8; nt++)
#pragma unroll
            for (int c = 0; c < 4; c++) acc[mt][nt][c] = 0.f;

    auto load_chunk = [&](int i) {
        const int st = i % 3;
        const int k0 = i * 64;
        const uint32_t ad = as_u + st * 128 * GKS * 2;
        const uint32_t wd = ws_u + st * 128 * GKS * 2;
#pragma unroll
        for (int j = 0; j < 4; j++) {
            int idx = tid + j * 256;          // 1024 chunks of 16B
            int row = idx >> 3, c = idx & 7;
            cp_async16(ad + (row * GKS + c * 8) * 2,
                       A + (size_t)(bm + row) * D_ + k0 + c * 8);
        }
#pragma unroll
        for (int j = 0; j < 4; j++) {
            int idx = tid + j * 256;
            int row = idx >> 3, c = idx & 7;
            cp_async16(wd + (row * GKS + c * 8) * 2,
                       Bt + (size_t)(bn + row) * D_ + k0 + c * 8);
        }
        CP_COMMIT();
    };

    load_chunk(0);
    load_chunk(1);

    for (int i = 0; i < 16; i++) {
        if (i < 15) {
            asm volatile("cp.async.wait_group 1;" ::: "memory");
        } else {
            asm volatile("cp.async.wait_group 0;" ::: "memory");
        }
        __syncthreads();

        const int st = i % 3;
        const uint32_t a_base = as_u + st * 128 * GKS * 2;
        const uint32_t b_base = ws_u + st * 128 * GKS * 2;

#pragma unroll
        for (int kt = 0; kt < 4; kt++) {
            uint32_t a0[4], a1[4];
            uint32_t arow = a_base +
                ((wm * 32 + (lane & 15)) * GKS + kt * 16 + (lane >> 4) * 8) * 2;
            ldsm_x4(a0[0], a0[1], a0[2], a0[3], arow);
            ldsm_x4(a1[0], a1[1], a1[2], a1[3], arow + 16 * GKS * 2);
#pragma unroll
            for (int ntp = 0; ntp < 4; ntp++) {
                uint32_t r0, r1, r2, r3;
                uint32_t baddr = b_base +
                    ((wn * 64 + ntp * 16 + (lane & 15)) * GKS + kt * 16 + (lane >> 4) * 8) * 2;
                ldsm_x4(r0, r1, r2, r3, baddr);
                // B pairs: (r0,r2) for n0-7, (r1,r3) for n8-15
                mma_f16(acc[0][2 * ntp],     a0[0], a0[1], a0[2], a0[3], r0, r2);
                mma_f16(acc[0][2 * ntp + 1], a0[0], a0[1], a0[2], a0[3], r1, r3);
                mma_f16(acc[1][2 * ntp],     a1[0], a1[1], a1[2], a1[3], r0, r2);
                mma_f16(acc[1][2 * ntp + 1], a1[0], a1[1], a1[2], a1[3], r1, r3);
            }
        }

        if (i + 2 < 16) load_chunk(i + 2);   // after sync: prior readers done
    }

    const float qs = (outMode == 2) ? (0.125f * LOG2E) : 1.0f;
#pragma unroll
    for (int mt = 0; mt < 2; mt++) {
#pragma unroll
        for (int half = 0; half < 2; half++) {
            int row = bm + wm * 32 + mt * 16 + g + half * 8;
#pragma unroll
            for (int nt = 0; nt < 8; nt++) {
                int col = bn + wn * 64 + nt * 8 + 2 * t;
                float vx = acc[mt][nt][half * 2 + 0] + bias[col + 0];
                float vy = acc[mt][nt][half * 2 + 1] + bias[col + 1];
                if (outMode == 0) {
                    *(float2*)&Cf[(size_t)row * D_ + col] = make_float2(vx, vy);
                } else {
                    int bb = row >> 11;
                    int ss = row & (S_ - 1);
                    int h  = col >> 6;
                    int dk = col & (DK_ - 1);
                    __half2 hv = __floats2half2_rn(vx * qs, vy * qs);
                    *(__half2*)&Ch[(size_t)(((bb << 4) + h) * S_ + ss) * DK_ + dk] = hv;
                }
            }
        }
    }
}

__global__ void __launch_bounds__(256, 2)
qkv_kernel(const float* __restrict__ bq, const float* __restrict__ bk,
           const float* __restrict__ bv)
{
    const float* bias; __half* dst; const __half* Bt; int mode;
    if (blockIdx.z == 0)      { bias = bq; dst = g_Qh; Bt = g_Wh;                       mode = 2; }
    else if (blockIdx.z == 1) { bias = bk; dst = g_Kh; Bt = g_Wh + (size_t)D_ * D_;     mode = 1; }
    else                      { bias = bv; dst = g_Vh; Bt = g_Wh + (size_t)2 * D_ * D_; mode = 1; }
    f16_gemm_body(g_Xh, Bt, bias, nullptr, dst, mode);
}

__global__ void __launch_bounds__(256, 2)
outproj_kernel(const float* __restrict__ bo, float* __restrict__ out)
{
    f16_gemm_body(g_ctx, g_Wh + (size_t)3 * D_ * D_, bo, out, nullptr, 0);
}

// ---------------------------------------------------------------------------
// fp16 flash attention. Block: 64 q x one (b,h), 4 warps (16 q-rows each),
// 128 threads -> 3 CTAs/SM, phase-independent (fills tensor-pipe softmax
// bubbles). KV tiles of 64, 3-stage cp.async (ONE sync/iter), ldmatrix
// fragments, half2 exp2 softmax, HADD2 rowsum, skip-rescale.
// Smem (half): Qs[64][72], Ks[3][64][72], Vs[3][64][72] = 64512 B
// ---------------------------------------------------------------------------
#define ATS 72
#define ATTN_SMEM ((64 * ATS + 3 * 64 * ATS + 3 * 64 * ATS) * 2)

__global__ void __launch_bounds__(128, 3)
attn_kernel()
{
    extern __shared__ __half smb[];
    const uint32_t qs_u = smem_u32(smb);
    const uint32_t ks_u = qs_u + 64 * ATS * 2;
    const uint32_t vs_u = ks_u + 3 * 64 * ATS * 2;

    const int tid  = threadIdx.x;
    const int lane = tid & 31;
    const int w    = tid >> 5;      // 0..3
    const int g    = lane >> 2;
    const int t    = lane & 3;
    const int wq   = w * 16;

    const int q0 = blockIdx.x * 64;
    const int h  = blockIdx.y;
    const int b  = blockIdx.z;
    const size_t headBase = (size_t)((b * H_) + h) * S_ * DK_;

    // Q tile (64 rows) -> smem (own group)
#pragma unroll
    for (int j = 0; j < 4; j++) {
        int idx = tid + j * 128;            // 512 chunks of 16B
        int row = idx >> 3, c = idx & 7;
        cp_async16(qs_u + (row * ATS + c * 8) * 2,
                   g_Qh + headBase + (size_t)(q0 + row) * DK_ + c * 8);
    }
    CP_COMMIT();

    auto load_kv = [&](int iter) {
        int st = iter % 3;
        int k0 = iter * 64;
        uint32_t kd = ks_u + st * 64 * ATS * 2;
        uint32_t vd = vs_u + st * 64 * ATS * 2;
#pragma unroll
        for (int j = 0; j < 4; j++) {
            int idx = tid + j * 128;        // 512 chunks
            int row = idx >> 3, c = idx & 7;
            cp_async16(kd + (row * ATS + c * 8) * 2,
                       g_Kh + headBase + (size_t)(k0 + row) * DK_ + c * 8);
        }
#pragma unroll
        for (int j = 0; j < 4; j++) {
            int idx = tid + j * 128;
            int row = idx >> 3, c = idx & 7;
            cp_async16(vd + (row * ATS + c * 8) * 2,
                       g_Vh + headBase + (size_t)(k0 + row) * DK_ + c * 8);
        }
        CP_COMMIT();
    };
    load_kv(0);
    load_kv(1);

    asm volatile("cp.async.wait_group 2;" ::: "memory");
    __syncthreads();

    uint32_t qa[4][4];
#pragma unroll
    for (int kt = 0; kt < 4; kt++) {
        uint32_t addr = qs_u + ((wq + (lane & 15)) * ATS + kt * 16 + (lane >> 4) * 8) * 2;
        ldsm_x4(qa[kt][0], qa[kt][1], qa[kt][2], qa[kt][3], addr);
    }

    float m0 = -1e30f, m1 = -1e30f, l0 = 0.f, l1 = 0.f;
    float o[8][4];
#pragma unroll
    for (int nt = 0; nt < 8; nt++)
#pragma unroll
        for (int c = 0; c < 4; c++) o[nt][c] = 0.f;

    for (int iter = 0; iter < 32; iter++) {
        if (iter < 31) {
            asm volatile("cp.async.wait_group 1;" ::: "memory");
        } else {
            asm volatile("cp.async.wait_group 0;" ::: "memory");
        }
        __syncthreads();

        const int st = iter % 3;
        const uint32_t kb_base = ks_u + st * 64 * ATS * 2;
        const uint32_t vb_base = vs_u + st * 64 * ATS * 2;

        // ---- S = Q @ K^T (base-2 logits) ----
        float s[8][4];
#pragma unroll
        for (int nt = 0; nt < 8; nt++)
#pragma unroll
            for (int c = 0; c < 4; c++) s[nt][c] = 0.f;

#pragma unroll
        for (int kt = 0; kt < 4; kt++) {
#pragma unroll
            for (int ntp = 0; ntp < 4; ntp++) {
                uint32_t r0, r1, r2, r3;
                uint32_t addr = kb_base +
                    ((ntp * 16 + (lane >> 4) * 8 + (lane & 7)) * ATS +
                     kt * 16 + ((lane >> 3) & 1) * 8) * 2;
                ldsm_x4(r0, r1, r2, r3, addr);
                mma_f16(s[2 * ntp],     qa[kt][0], qa[kt][1], qa[kt][2], qa[kt][3], r0, r1);
                mma_f16(s[2 * ntp + 1], qa[kt][0], qa[kt][1], qa[kt][2], qa[kt][3], r2, r3);
            }
        }

        // ---- Online softmax (rows g, g+8), base 2, half2 exp ----
        float mx0 = -1e30f, mx1 = -1e30f;
#pragma unroll
        for (int nt = 0; nt < 8; nt++) {
            mx0 = fmaxf(mx0, fmaxf(s[nt][0], s[nt][1]));
            mx1 = fmaxf(mx1, fmaxf(s[nt][2], s[nt][3]));
        }
        mx0 = fmaxf(mx0, __shfl_xor_sync(0xffffffffu, mx0, 1));
        mx0 = fmaxf(mx0, __shfl_xor_sync(0xffffffffu, mx0, 2));
        mx1 = fmaxf(mx1, __shfl_xor_sync(0xffffffffu, mx1, 1));
        mx1 = fmaxf(mx1, __shfl_xor_sync(0xffffffffu, mx1, 2));

        float m0n = fmaxf(m0, mx0);
        float m1n = fmaxf(m1, mx1);
        float alpha0 = ex2f(m0 - m0n);
        float alpha1 = ex2f(m1 - m1n);
        m0 = m0n; m1 = m1n;

        __half2 m0h = __floats2half2_rn(m0n, m0n);
        __half2 m1h = __floats2half2_rn(m1n, m1n);
        uint32_t pf[8][2];
#pragma unroll
        for (int nt = 0; nt < 8; nt++) {
            __half2 sh0 = __hsub2(__floats2half2_rn(s[nt][0], s[nt][1]), m0h);
            __half2 sh1 = __hsub2(__floats2half2_rn(s[nt][2], s[nt][3]), m1h);
            pf[nt][0] = ex2_h2(sh0);
            pf[nt][1] = ex2_h2(sh1);
        }

        // ---- rescale O and l (skipped when max unchanged) ----
        if (alpha0 != 1.0f || alpha1 != 1.0f) {
#pragma unroll
            for (int nt = 0; nt < 8; nt++) {
                o[nt][0] *= alpha0; o[nt][1] *= alpha0;
                o[nt][2] *= alpha1; o[nt][3] *= alpha1;
            }
            l0 *= alpha0; l1 *= alpha1;
        }

        // ---- l += rowsum(P) via HADD2 (keeps tensor pipe free) ----
        {
            __half2 a0 = *(__half2*)&pf[0][0];
            __half2 a1 = *(__half2*)&pf[0][1];
#pragma unroll
            for (int nt = 1; nt < 8; nt++) {
                a0 = __hadd2(a0, *(__half2*)&pf[nt][0]);
                a1 = __hadd2(a1, *(__half2*)&pf[nt][1]);
            }
            float sum0 = __low2float(a0) + __high2float(a0);
            float sum1 = __low2float(a1) + __high2float(a1);
            sum0 += __shfl_xor_sync(0xffffffffu, sum0, 1);
            sum0 += __shfl_xor_sync(0xffffffffu, sum0, 2);
            sum1 += __shfl_xor_sync(0xffffffffu, sum1, 1);
            sum1 += __shfl_xor_sync(0xffffffffu, sum1, 2);
            l0 += sum0;
            l1 += sum1;
        }

        // ---- O += P @ V ----
#pragma unroll
        for (int kt = 0; kt < 4; kt++) {
            uint32_t a0 = pf[2 * kt][0];
            uint32_t a1 = pf[2 * kt][1];
            uint32_t a2 = pf[2 * kt + 1][0];
            uint32_t a3 = pf[2 * kt + 1][1];
#pragma unroll
            for (int ntp = 0; ntp < 4; ntp++) {
                uint32_t r0, r1, r2, r3;
                uint32_t addr = vb_base +
                    ((kt * 16 + ((lane >> 3) & 1) * 8 + (lane & 7)) * ATS +
                     ntp * 16 + (lane >> 4) * 8) * 2;
                ldsm_x4_t(r0, r1, r2, r3, addr);
                mma_f16(o[2 * ntp],     a0, a1, a2, a3, r0, r1);
                mma_f16(o[2 * ntp + 1], a0, a1, a2, a3, r2, r3);
            }
        }

        if (iter + 2 < 32) load_kv(iter + 2);
    }

    // ---- Normalize and store ctx (fp16) ----
    float inv0 = 1.0f / l0;
    float inv1 = 1.0f / l1;
    int row0 = b * S_ + q0 + wq + g;
    int row1 = row0 + 8;
#pragma unroll
    for (int nt = 0; nt < 8; nt++) {
        int col = h * DK_ + nt * 8 + 2 * t;
        __half2 v0 = __floats2half2_rn(o[nt][0] * inv0, o[nt][1] * inv0);
        __half2 v1 = __floats2half2_rn(o[nt][2] * inv1, o[nt][3] * inv1);
        *(__half2*)&g_ctx[(size_t)row0 * D_ + col] = v0;
        *(__half2*)&g_ctx[(size_t)row1 * D_ + col] = v1;
    }
}

// ---------------------------------------------------------------------------
// Launch
// ---------------------------------------------------------------------------
extern "C" void kernel_launch(void* const* d_in, const int* in_sizes, int n_in,
                              void* d_out, int out_size)
{
    const float* query = (const float*)d_in[0];
    const float* Wq = (const float*)d_in[1];
    const float* bq = (const float*)d_in[2];
    const float* Wk = (const float*)d_in[3];
    const float* bk = (const float*)d_in[4];
    const float* Wv = (const float*)d_in[5];
    const float* bv = (const float*)d_in[6];
    const float* Wo = (const float*)d_in[7];
    const float* bo = (const float*)d_in[8];
    float* out = (float*)d_out;

    cudaFuncSetAttribute(qkv_kernel, cudaFuncAttributeMaxDynamicSharedMemorySize, GEMM_SMEM);
    cudaFuncSetAttribute(outproj_kernel, cudaFuncAttributeMaxDynamicSharedMemorySize, GEMM_SMEM);
    cudaFuncSetAttribute(attn_kernel, cudaFuncAttributeMaxDynamicSharedMemorySize, ATTN_SMEM);

    prep_kernel<<<dim3(32, 32, 6), dim3(32, 8)>>>(query, Wq, Wk, Wv, Wo);

    qkv_kernel<<<dim3(8, 32, 3), 256, GEMM_SMEM>>>(bq, bk, bv);
    attn_kernel<<<dim3(S_ / 64, H_, B_), 128, ATTN_SMEM>>>();
    outproj_kernel<<<dim3(8, 32), 256, GEMM_SMEM>>>(bo, out);
}

// round 10
// speedup vs baseline: 7.2658x; 1.0249x over previous
#include <cuda_runtime.h>
#include <cuda_fp16.h>
#include <cstdint>

// Problem constants
#define B_   2
#define S_   2048
#define D_   1024
#define H_   16
#define DK_  64
#define M_   (B_ * S_)   // 4096

#define LOG2E 1.4426950408889634f

// ---------------------------------------------------------------------------
// Scratch (device globals)
// ---------------------------------------------------------------------------
__device__ __align__(16) __half g_Xh[M_ * D_];            // fp16 input
__device__ __align__(16) __half g_Wh[4 * D_ * D_];        // [N][K] fp16 weights (q,k,v,o)
__device__ __align__(16) __half g_Qh[B_ * H_ * S_ * DK_]; // Q * (1/8 * log2e)
__device__ __align__(16) __half g_Kh[B_ * H_ * S_ * DK_];
__device__ __align__(16) __half g_Vh[B_ * H_ * S_ * DK_];
__device__ __align__(16) __half g_ctx[M_ * D_];           // attention out, fp16

// ---------------------------------------------------------------------------
// Helpers
// ---------------------------------------------------------------------------
__device__ __forceinline__ uint32_t smem_u32(const void* p) {
    uint32_t a;
    asm("{ .reg .u64 t; cvta.to.shared.u64 t, %1; cvt.u32.u64 %0, t; }"
        : "=r"(a) : "l"(p));
    return a;
}

__device__ __forceinline__ void cp_async16(uint32_t dst, const void* src) {
    asm volatile("cp.async.cg.shared.global [%0], [%1], 16;"
                 :: "r"(dst), "l"(src));
}
#define CP_COMMIT() asm volatile("cp.async.commit_group;" ::: "memory")

__device__ __forceinline__ float ex2f(float x) {
    float r;
    asm("ex2.approx.f32 %0, %1;" : "=f"(r) : "f"(x));
    return r;
}

// packed half2 exp2
__device__ __forceinline__ uint32_t ex2_h2(__half2 x) {
    uint32_t xi = *(uint32_t*)&x, r;
    asm("ex2.approx.f16x2 %0, %1;" : "=r"(r) : "r"(xi));
    return r;
}

// fp16 mma, fp32 accumulate
__device__ __forceinline__ void mma_f16(float* c,
                                        uint32_t a0, uint32_t a1,
                                        uint32_t a2, uint32_t a3,
                                        uint32_t b0, uint32_t b1) {
    asm volatile(
        "mma.sync.aligned.m16n8k16.row.col.f32.f16.f16.f32 "
        "{%0,%1,%2,%3}, {%4,%5,%6,%7}, {%8,%9}, {%0,%1,%2,%3};"
        : "+f"(c[0]), "+f"(c[1]), "+f"(c[2]), "+f"(c[3])
        : "r"(a0), "r"(a1), "r"(a2), "r"(a3), "r"(b0), "r"(b1));
}

__device__ __forceinline__ void ldsm_x4(uint32_t& r0, uint32_t& r1,
                                        uint32_t& r2, uint32_t& r3, uint32_t a) {
    asm volatile("ldmatrix.sync.aligned.m8n8.x4.shared.b16 {%0,%1,%2,%3}, [%4];"
                 : "=r"(r0), "=r"(r1), "=r"(r2), "=r"(r3) : "r"(a));
}
__device__ __forceinline__ void ldsm_x4_t(uint32_t& r0, uint32_t& r1,
                                          uint32_t& r2, uint32_t& r3, uint32_t a) {
    asm volatile("ldmatrix.sync.aligned.m8n8.x4.trans.shared.b16 {%0,%1,%2,%3}, [%4];"
                 : "=r"(r0), "=r"(r1), "=r"(r2), "=r"(r3) : "r"(a));
}

__device__ __forceinline__ uint32_t pack_h2(float lo, float hi) {
    __half2 h = __floats2half2_rn(lo, hi);
    return *(uint32_t*)&h;
}

// ---------------------------------------------------------------------------
// Merged prep: z=0..3 -> weight transpose+convert to [N][K] fp16;
//              z=4..5 -> input fp32->fp16 convert.
// grid (32, 32, 6), block (32, 8)
// ---------------------------------------------------------------------------
__global__ void __launch_bounds__(256)
prep_kernel(const float* __restrict__ X,
            const float* __restrict__ Wq, const float* __restrict__ Wk,
            const float* __restrict__ Wv, const float* __restrict__ Wo)
{
    const int z = blockIdx.z;
    if (z < 4) {
        __shared__ float t[32][33];
        const float* W = (z == 0) ? Wq : (z == 1) ? Wk : (z == 2) ? Wv : Wo;
        __half* out = g_Wh + (size_t)z * D_ * D_;
        int n0 = blockIdx.x * 32;
        int k0 = blockIdx.y * 32;
        int x = threadIdx.x, y0 = threadIdx.y;
#pragma unroll
        for (int dy = 0; dy < 32; dy += 8)
            t[y0 + dy][x] = W[(size_t)(k0 + y0 + dy) * D_ + n0 + x];
        __syncthreads();
#pragma unroll
        for (int dy = 0; dy < 32; dy += 8)
            out[(size_t)(n0 + y0 + dy) * D_ + k0 + x] = __float2half_rn(t[x][y0 + dy]);
    } else {
        int tid = threadIdx.y * 32 + threadIdx.x;
        int i = ((z - 4) * 1024 + blockIdx.y * 32 + blockIdx.x) * 256 + tid;
        float4 v0 = ((const float4*)X)[2 * i];
        float4 v1 = ((const float4*)X)[2 * i + 1];
        uint4 o;
        o.x = pack_h2(v0.x, v0.y);
        o.y = pack_h2(v0.z, v0.w);
        o.z = pack_h2(v1.x, v1.y);
        o.w = pack_h2(v1.z, v1.w);
        ((uint4*)g_Xh)[i] = o;
    }
}

// ---------------------------------------------------------------------------
// fp16 mma GEMM: C[M x 1024] = A[M x 1024] @ Wt^T + bias
// CTA 128x128, 8 warps, K chunks of 64, 3-stage cp.async, ONE sync per iter.
// Inner loop issues ALL ldsm for a k-step first, then the mma burst
// (one exposed LDS latency per k-step instead of four).
// outMode: 0 = fp32 row-major, 1 = fp16 [B][H][S][DK], 2 = same scaled by 1/8*log2e
// ---------------------------------------------------------------------------
#define GKS 72
#define GEMM_SMEM (3 * 2 * 128 * GKS * 2)   // 110592 bytes

__device__ __forceinline__ void f16_gemm_body(const __half* __restrict__ A,
                                              const __half* __restrict__ Bt,
                                              const float* __restrict__ bias,
                                              float* __restrict__ Cf,
                                              __half* __restrict__ Ch,
                                              int outMode)
{
    extern __shared__ __half smh[];
    const uint32_t as_u = smem_u32(smh);                       // [3][128][GKS]
    const uint32_t ws_u = as_u + 3 * 128 * GKS * 2;            // [3][128][GKS]

    const int tid  = threadIdx.x;
    const int lane = tid & 31;
    const int w    = tid >> 5;
    const int wm   = w >> 1;          // 0..3
    const int wn   = w & 1;           // 0..1
    const int g    = lane >> 2;
    const int t    = lane & 3;
    const int bm   = blockIdx.y * 128;
    const int bn   = blockIdx.x * 128;

    float acc[2][8][4];
#pragma unroll
    for (int mt = 0; mt < 2; mt++)
#pragma unroll
        for (int nt = 0; nt < 8; nt++)
#pragma unroll
            for (int c = 0; c < 4; c++) acc[mt][nt][c] = 0.f;

    auto load_chunk = [&](int i) {
        const int st = i % 3;
        const int k0 = i * 64;
        const uint32_t ad = as_u + st * 128 * GKS * 2;
        const uint32_t wd = ws_u + st * 128 * GKS * 2;
#pragma unroll
        for (int j = 0; j < 4; j++) {
            int idx = tid + j * 256;          // 1024 chunks of 16B
            int row = idx >> 3, c = idx & 7;
            cp_async16(ad + (row * GKS + c * 8) * 2,
                       A + (size_t)(bm + row) * D_ + k0 + c * 8);
        }
#pragma unroll
        for (int j = 0; j < 4; j++) {
            int idx = tid + j * 256;
            int row = idx >> 3, c = idx & 7;
            cp_async16(wd + (row * GKS + c * 8) * 2,
                       Bt + (size_t)(bn + row) * D_ + k0 + c * 8);
        }
        CP_COMMIT();
    };

    load_chunk(0);
    load_chunk(1);

    for (int i = 0; i < 16; i++) {
        if (i < 15) {
            asm volatile("cp.async.wait_group 1;" ::: "memory");
        } else {
            asm volatile("cp.async.wait_group 0;" ::: "memory");
        }
        __syncthreads();

        const int st = i % 3;
        const uint32_t a_base = as_u + st * 128 * GKS * 2;
        const uint32_t b_base = ws_u + st * 128 * GKS * 2;

#pragma unroll
        for (int kt = 0; kt < 4; kt++) {
            uint32_t a0[4], a1[4], bf[4][4];
            uint32_t arow = a_base +
                ((wm * 32 + (lane & 15)) * GKS + kt * 16 + (lane >> 4) * 8) * 2;
            ldsm_x4(a0[0], a0[1], a0[2], a0[3], arow);
            ldsm_x4(a1[0], a1[1], a1[2], a1[3], arow + 16 * GKS * 2);
#pragma unroll
            for (int ntp = 0; ntp < 4; ntp++) {
                uint32_t baddr = b_base +
                    ((wn * 64 + ntp * 16 + (lane & 15)) * GKS + kt * 16 + (lane >> 4) * 8) * 2;
                ldsm_x4(bf[ntp][0], bf[ntp][1], bf[ntp][2], bf[ntp][3], baddr);
            }
#pragma unroll
            for (int ntp = 0; ntp < 4; ntp++) {
                // B pairs: (r0,r2) for n0-7, (r1,r3) for n8-15
                mma_f16(acc[0][2 * ntp],     a0[0], a0[1], a0[2], a0[3], bf[ntp][0], bf[ntp][2]);
                mma_f16(acc[0][2 * ntp + 1], a0[0], a0[1], a0[2], a0[3], bf[ntp][1], bf[ntp][3]);
                mma_f16(acc[1][2 * ntp],     a1[0], a1[1], a1[2], a1[3], bf[ntp][0], bf[ntp][2]);
                mma_f16(acc[1][2 * ntp + 1], a1[0], a1[1], a1[2], a1[3], bf[ntp][1], bf[ntp][3]);
            }
        }

        if (i + 2 < 16) load_chunk(i + 2);   // after sync: prior readers done
    }

    const float qs = (outMode == 2) ? (0.125f * LOG2E) : 1.0f;
#pragma unroll
    for (int mt = 0; mt < 2; mt++) {
#pragma unroll
        for (int half = 0; half < 2; half++) {
            int row = bm + wm * 32 + mt * 16 + g + half * 8;
#pragma unroll
            for (int nt = 0; nt < 8; nt++) {
                int col = bn + wn * 64 + nt * 8 + 2 * t;
                float vx = acc[mt][nt][half * 2 + 0] + bias[col + 0];
                float vy = acc[mt][nt][half * 2 + 1] + bias[col + 1];
                if (outMode == 0) {
                    *(float2*)&Cf[(size_t)row * D_ + col] = make_float2(vx, vy);
                } else {
                    int bb = row >> 11;
                    int ss = row & (S_ - 1);
                    int h  = col >> 6;
                    int dk = col & (DK_ - 1);
                    __half2 hv = __floats2half2_rn(vx * qs, vy * qs);
                    *(__half2*)&Ch[(size_t)(((bb << 4) + h) * S_ + ss) * DK_ + dk] = hv;
                }
            }
        }
    }
}

__global__ void __launch_bounds__(256, 2)
qkv_kernel(const float* __restrict__ bq, const float* __restrict__ bk,
           const float* __restrict__ bv)
{
    const float* bias; __half* dst; const __half* Bt; int mode;
    if (blockIdx.z == 0)      { bias = bq; dst = g_Qh; Bt = g_Wh;                       mode = 2; }
    else if (blockIdx.z == 1) { bias = bk; dst = g_Kh; Bt = g_Wh + (size_t)D_ * D_;     mode = 1; }
    else                      { bias = bv; dst = g_Vh; Bt = g_Wh + (size_t)2 * D_ * D_; mode = 1; }
    f16_gemm_body(g_Xh, Bt, bias, nullptr, dst, mode);
}

__global__ void __launch_bounds__(256, 2)
outproj_kernel(const float* __restrict__ bo, float* __restrict__ out)
{
    f16_gemm_body(g_ctx, g_Wh + (size_t)3 * D_ * D_, bo, out, nullptr, 0);
}

// ---------------------------------------------------------------------------
// fp16 flash attention. Block: 64 q x one (b,h), 4 warps (16 q-rows each),
// 128 threads -> 4 CTAs/SM (Q smem eliminated; fragments loaded directly
// from gmem with per-lane addressing). KV tiles of 64, 3-stage cp.async
// (ONE sync/iter), grouped ldsm->mma bursts, half2 exp2 softmax,
// HADD2 rowsum, skip-rescale.
// Smem (half): Ks[3][64][72], Vs[3][64][72] = 55296 B -> 4 CTAs/SM
// ---------------------------------------------------------------------------
#define ATS 72
#define ATTN_SMEM ((3 * 64 * ATS + 3 * 64 * ATS) * 2)   // 55296

__global__ void __launch_bounds__(128, 4)
attn_kernel()
{
    extern __shared__ __half smb[];
    const uint32_t ks_u = smem_u32(smb);
    const uint32_t vs_u = ks_u + 3 * 64 * ATS * 2;

    const int tid  = threadIdx.x;
    const int lane = tid & 31;
    const int w    = tid >> 5;      // 0..3
    const int g    = lane >> 2;
    const int t    = lane & 3;
    const int wq   = w * 16;

    const int q0 = blockIdx.x * 64;
    const int h  = blockIdx.y;
    const int b  = blockIdx.z;
    const size_t headBase = (size_t)((b * H_) + h) * S_ * DK_;

    auto load_kv = [&](int iter) {
        int st = iter % 3;
        int k0 = iter * 64;
        uint32_t kd = ks_u + st * 64 * ATS * 2;
        uint32_t vd = vs_u + st * 64 * ATS * 2;
#pragma unroll
        for (int j = 0; j < 4; j++) {
            int idx = tid + j * 128;        // 512 chunks of 16B
            int row = idx >> 3, c = idx & 7;
            cp_async16(kd + (row * ATS + c * 8) * 2,
                       g_Kh + headBase + (size_t)(k0 + row) * DK_ + c * 8);
        }
#pragma unroll
        for (int j = 0; j < 4; j++) {
            int idx = tid + j * 128;
            int row = idx >> 3, c = idx & 7;
            cp_async16(vd + (row * ATS + c * 8) * 2,
                       g_Vh + headBase + (size_t)(k0 + row) * DK_ + c * 8);
        }
        CP_COMMIT();
    };
    load_kv(0);
    load_kv(1);

    // Q fragments straight from gmem (per-lane m16n8k16 A layout);
    // latency hidden behind the kv0 cp.async wait.
    uint32_t qa[4][4];
    {
        const __half* Qb = g_Qh + headBase + (size_t)(q0 + wq + g) * DK_ + 2 * t;
#pragma unroll
        for (int kt = 0; kt < 4; kt++) {
            qa[kt][0] = *(const uint32_t*)(Qb + kt * 16);
            qa[kt][1] = *(const uint32_t*)(Qb + 8 * DK_ + kt * 16);
            qa[kt][2] = *(const uint32_t*)(Qb + kt * 16 + 8);
            qa[kt][3] = *(const uint32_t*)(Qb + 8 * DK_ + kt * 16 + 8);
        }
    }

    float m0 = -1e30f, m1 = -1e30f, l0 = 0.f, l1 = 0.f;
    float o[8][4];
#pragma unroll
    for (int nt = 0; nt < 8; nt++)
#pragma unroll
        for (int c = 0; c < 4; c++) o[nt][c] = 0.f;

    for (int iter = 0; iter < 32; iter++) {
        if (iter < 31) {
            asm volatile("cp.async.wait_group 1;" ::: "memory");
        } else {
            asm volatile("cp.async.wait_group 0;" ::: "memory");
        }
        __syncthreads();

        const int st = iter % 3;
        const uint32_t kb_base = ks_u + st * 64 * ATS * 2;
        const uint32_t vb_base = vs_u + st * 64 * ATS * 2;

        // ---- S = Q @ K^T (base-2 logits); grouped ldsm then mma burst ----
        float s[8][4];
#pragma unroll
        for (int nt = 0; nt < 8; nt++)
#pragma unroll
            for (int c = 0; c < 4; c++) s[nt][c] = 0.f;

#pragma unroll
        for (int kt = 0; kt < 4; kt++) {
            uint32_t kf[4][4];
#pragma unroll
            for (int ntp = 0; ntp < 4; ntp++) {
                uint32_t addr = kb_base +
                    ((ntp * 16 + (lane >> 4) * 8 + (lane & 7)) * ATS +
                     kt * 16 + ((lane >> 3) & 1) * 8) * 2;
                ldsm_x4(kf[ntp][0], kf[ntp][1], kf[ntp][2], kf[ntp][3], addr);
            }
#pragma unroll
            for (int ntp = 0; ntp < 4; ntp++) {
                mma_f16(s[2 * ntp],     qa[kt][0], qa[kt][1], qa[kt][2], qa[kt][3],
                        kf[ntp][0], kf[ntp][1]);
                mma_f16(s[2 * ntp + 1], qa[kt][0], qa[kt][1], qa[kt][2], qa[kt][3],
                        kf[ntp][2], kf[ntp][3]);
            }
        }

        // ---- Online softmax (rows g, g+8), base 2, half2 exp ----
        float mx0 = -1e30f, mx1 = -1e30f;
#pragma unroll
        for (int nt = 0; nt < 8; nt++) {
            mx0 = fmaxf(mx0, fmaxf(s[nt][0], s[nt][1]));
            mx1 = fmaxf(mx1, fmaxf(s[nt][2], s[nt][3]));
        }
        mx0 = fmaxf(mx0, __shfl_xor_sync(0xffffffffu, mx0, 1));
        mx0 = fmaxf(mx0, __shfl_xor_sync(0xffffffffu, mx0, 2));
        mx1 = fmaxf(mx1, __shfl_xor_sync(0xffffffffu, mx1, 1));
        mx1 = fmaxf(mx1, __shfl_xor_sync(0xffffffffu, mx1, 2));

        float m0n = fmaxf(m0, mx0);
        float m1n = fmaxf(m1, mx1);
        float alpha0 = ex2f(m0 - m0n);
        float alpha1 = ex2f(m1 - m1n);
        m0 = m0n; m1 = m1n;

        __half2 m0h = __floats2half2_rn(m0n, m0n);
        __half2 m1h = __floats2half2_rn(m1n, m1n);
        uint32_t pf[8][2];
#pragma unroll
        for (int nt = 0; nt < 8; nt++) {
            __half2 sh0 = __hsub2(__floats2half2_rn(s[nt][0], s[nt][1]), m0h);
            __half2 sh1 = __hsub2(__floats2half2_rn(s[nt][2], s[nt][3]), m1h);
            pf[nt][0] = ex2_h2(sh0);
            pf[nt][1] = ex2_h2(sh1);
        }

        // ---- rescale O and l (skipped when max unchanged) ----
        if (alpha0 != 1.0f || alpha1 != 1.0f) {
#pragma unroll
            for (int nt = 0; nt < 8; nt++) {
                o[nt][0] *= alpha0; o[nt][1] *= alpha0;
                o[nt][2] *= alpha1; o[nt][3] *= alpha1;
            }
            l0 *= alpha0; l1 *= alpha1;
        }

        // ---- l += rowsum(P) via HADD2 (keeps tensor pipe free) ----
        {
            __half2 a0 = *(__half2*)&pf[0][0];
            __half2 a1 = *(__half2*)&pf[0][1];
#pragma unroll
            for (int nt = 1; nt < 8; nt++) {
                a0 = __hadd2(a0, *(__half2*)&pf[nt][0]);
                a1 = __hadd2(a1, *(__half2*)&pf[nt][1]);
            }
            float sum0 = __low2float(a0) + __high2float(a0);
            float sum1 = __low2float(a1) + __high2float(a1);
            sum0 += __shfl_xor_sync(0xffffffffu, sum0, 1);
            sum0 += __shfl_xor_sync(0xffffffffu, sum0, 2);
            sum1 += __shfl_xor_sync(0xffffffffu, sum1, 1);
            sum1 += __shfl_xor_sync(0xffffffffu, sum1, 2);
            l0 += sum0;
            l1 += sum1;
        }

        // ---- O += P @ V; grouped ldsm then mma burst ----
#pragma unroll
        for (int kt = 0; kt < 4; kt++) {
            uint32_t a0 = pf[2 * kt][0];
            uint32_t a1 = pf[2 * kt][1];
            uint32_t a2 = pf[2 * kt + 1][0];
            uint32_t a3 = pf[2 * kt + 1][1];
            uint32_t vf[4][4];
#pragma unroll
            for (int ntp = 0; ntp < 4; ntp++) {
                uint32_t addr = vb_base +
                    ((kt * 16 + ((lane >> 3) & 1) * 8 + (lane & 7)) * ATS +
                     ntp * 16 + (lane >> 4) * 8) * 2;
                ldsm_x4_t(vf[ntp][0], vf[ntp][1], vf[ntp][2], vf[ntp][3], addr);
            }
#pragma unroll
            for (int ntp = 0; ntp < 4; ntp++) {
                mma_f16(o[2 * ntp],     a0, a1, a2, a3, vf[ntp][0], vf[ntp][1]);
                mma_f16(o[2 * ntp + 1], a0, a1, a2, a3, vf[ntp][2], vf[ntp][3]);
            }
        }

        if (iter + 2 < 32) load_kv(iter + 2);
    }

    // ---- Normalize and store ctx (fp16) ----
    float inv0 = 1.0f / l0;
    float inv1 = 1.0f / l1;
    int row0 = b * S_ + q0 + wq + g;
    int row1 = row0 + 8;
#pragma unroll
    for (int nt = 0; nt < 8; nt++) {
        int col = h * DK_ + nt * 8 + 2 * t;
        __half2 v0 = __floats2half2_rn(o[nt][0] * inv0, o[nt][1] * inv0);
        __half2 v1 = __floats2half2_rn(o[nt][2] * inv1, o[nt][3] * inv1);
        *(__half2*)&g_ctx[(size_t)row0 * D_ + col] = v0;
        *(__half2*)&g_ctx[(size_t)row1 * D_ + col] = v1;
    }
}

// ---------------------------------------------------------------------------
// Launch
// ---------------------------------------------------------------------------
extern "C" void kernel_launch(void* const* d_in, const int* in_sizes, int n_in,
                              void* d_out, int out_size)
{
    const float* query = (const float*)d_in[0];
    const float* Wq = (const float*)d_in[1];
    const float* bq = (const float*)d_in[2];
    const float* Wk = (const float*)d_in[3];
    const float* bk = (const float*)d_in[4];
    const float* Wv = (const float*)d_in[5];
    const float* bv = (const float*)d_in[6];
    const float* Wo = (const float*)d_in[7];
    const float* bo = (const float*)d_in[8];
    float* out = (float*)d_out;

    cudaFuncSetAttribute(qkv_kernel, cudaFuncAttributeMaxDynamicSharedMemorySize, GEMM_SMEM);
    cudaFuncSetAttribute(outproj_kernel, cudaFuncAttributeMaxDynamicSharedMemorySize, GEMM_SMEM);
    cudaFuncSetAttribute(attn_kernel, cudaFuncAttributeMaxDynamicSharedMemorySize, ATTN_SMEM);

    prep_kernel<<<dim3(32, 32, 6), dim3(32, 8)>>>(query, Wq, Wk, Wv, Wo);

    qkv_kernel<<<dim3(8, 32, 3), 256, GEMM_SMEM>>>(bq, bk, bv);
    attn_kernel<<<dim3(S_ / 64, H_, B_), 128, ATTN_SMEM>>>();
    outproj_kernel<<<dim3(8, 32), 256, GEMM_SMEM>>>(bo, out);
}